// round 10
// baseline (speedup 1.0000x reference)
#include <cuda_runtime.h>
#include <cstdint>

#define NN 50000
#define NE 640000

__device__ float g_y2[(size_t)NE * 128];   // raw edge-MLP outputs (no be2)
__device__ float g_U[(size_t)NN * 128];    // node_h @ We1[0:128]
__device__ float g_V[(size_t)NN * 128];    // node_h @ We1[128:256]
__device__ float g_P[(size_t)NN * 128];    // node_h @ Wn1[128:256]
__device__ int g_cnt[NN], g_off[NN + 1], g_cur[NN], g_eord[NE];
// weight slab images, transposed [128 N x 64 K] bf16 row-major (128B/row):
// We1:0-5, We2:6-7, Wn1:8-11, Wn2:12-13
__device__ __align__(16) unsigned char g_Wh[14 * 16384];
__device__ __align__(16) unsigned char g_Wl[14 * 16384];

static __device__ __forceinline__ uint32_t smem_u32(const void* p) {
    uint32_t a;
    asm("{ .reg .u64 t; cvta.to.shared.u64 t, %1; cvt.u32.u64 %0, t; }" : "=r"(a) : "l"(p));
    return a;
}
static __device__ __forceinline__ uint32_t prmt_hi16(uint32_t a, uint32_t b) {
    uint32_t r; asm("prmt.b32 %0,%1,%2,0x7632;" : "=r"(r) : "r"(a), "r"(b)); return r;
}
static __device__ __forceinline__ float trh(float x) {
    return __uint_as_float(__float_as_uint(x) & 0xFFFF0000u);
}
static __device__ __forceinline__ uint32_t bf2(float hi_, float lo_) {
    uint32_t r; asm("cvt.rn.bf16x2.f32 %0,%1,%2;" : "=r"(r) : "f"(hi_), "f"(lo_)); return r;
}

#define CPA(dst, src) asm volatile("cp.async.ca.shared.global [%0], [%1], 16;" :: "r"(dst), "l"(src))
#define CPC()         asm volatile("cp.async.commit_group;" ::: "memory")
#define CPW(n)        asm volatile("cp.async.wait_group %0;" :: "n"(n) : "memory")

static __device__ __forceinline__ void ldsm4(uint32_t addr, uint32_t* r) {
    asm volatile("ldmatrix.sync.aligned.m8n8.x4.shared.b16 {%0,%1,%2,%3}, [%4];"
                 : "=r"(r[0]), "=r"(r[1]), "=r"(r[2]), "=r"(r[3]) : "r"(addr));
}
static __device__ __forceinline__ void mma16816(float* d, const uint32_t* a, const uint32_t* b) {
    asm volatile("mma.sync.aligned.m16n8k16.row.col.f32.bf16.bf16.f32 "
                 "{%0,%1,%2,%3},{%4,%5,%6,%7},{%8,%9},{%0,%1,%2,%3};"
                 : "+f"(d[0]), "+f"(d[1]), "+f"(d[2]), "+f"(d[3])
                 : "r"(a[0]), "r"(a[1]), "r"(a[2]), "r"(a[3]), "r"(b[0]), "r"(b[1]));
}

// SMEM: 64-row A tiles (hi/lo, double-buffered) + 128-row B (hi/lo, single)
#define OFF_DST  0
#define OFF_ROWS 256
#define ABUF     9216                     // 64 * 144
#define OFF_AH(b) (2048 + (b) * ABUF)     // AH0,AH1 contiguous (Y hi reuse)
#define OFF_AL(b) (2048 + 2 * ABUF + (b) * ABUF)
#define OFF_BH    (2048 + 4 * ABUF)       // 128 * 144 = 18432
#define OFF_BL    (OFF_BH + 18432)
#define SM_BYTES  (2048 + 4 * ABUF + 2 * 18432)   // 75776
#define SM_EIDS   SM_BYTES                 // node kernel: edge-id stage after main area
#define EID_CAP   2048
#define SM_BYTES_NODE (SM_BYTES + EID_CAP * 4)    // 83968
#define ASTR 144
#define YSTR 272

#define ZACC(a) do {                                                   \
    _Pragma("unroll") for (int _m = 0; _m < 2; _m++)                   \
    _Pragma("unroll") for (int _n = 0; _n < 8; _n++)                   \
    _Pragma("unroll") for (int _q = 0; _q < 4; _q++) (a)[_m][_n][_q] = 0.f; } while (0)

// one K=16 chunk, 3-term compensated: 12 LDSM + 48 MMA (warp: 32 rows x 64 cols)
static __device__ __forceinline__ void mma_chunk(
        uint32_t ahb, uint32_t alb, int astride, uint32_t bhb, uint32_t blb,
        int mrow, int nbase, int kb, int bkb, int lane, float acc[2][8][4]) {
    uint32_t ah[2][4], al[2][4], bh[4][4], bl[4][4];
    const int arow = mrow + (lane & 15);
    const int ak   = kb + (lane >> 4) * 16;
#pragma unroll
    for (int mt = 0; mt < 2; mt++) {
        uint32_t off = (uint32_t)((arow + 16 * mt) * astride + ak);
        ldsm4(ahb + off, ah[mt]);
        ldsm4(alb + off, al[mt]);
    }
    const int bn = (lane & 7) + 8 * (lane >> 4);
    const int bk = bkb + ((lane >> 3) & 1) * 16;
#pragma unroll
    for (int nt2 = 0; nt2 < 4; nt2++) {
        uint32_t off = (uint32_t)((nbase + 16 * nt2 + bn) * ASTR + bk);
        ldsm4(bhb + off, bh[nt2]);
        ldsm4(blb + off, bl[nt2]);
    }
#pragma unroll
    for (int mt = 0; mt < 2; mt++)
#pragma unroll
        for (int nt = 0; nt < 8; nt++) {
            const uint32_t* bhp = &bh[nt >> 1][2 * (nt & 1)];
            const uint32_t* blp = &bl[nt >> 1][2 * (nt & 1)];
            mma16816(acc[mt][nt], ah[mt], bhp);
            mma16816(acc[mt][nt], ah[mt], blp);
            mma16816(acc[mt][nt], al[mt], bhp);
        }
}

// ---- loaders (128 threads) ----
static __device__ __forceinline__ void load_W(uint32_t sb, int slab, int tid) {
    for (int u = tid; u < 2048; u += 128) {
        int isLo = u >> 10, uu = u & 1023, r = uu >> 3, c = uu & 7;
        const unsigned char* g = (isLo ? g_Wl : g_Wh) + slab * 16384;
        CPA(sb + (isLo ? OFF_BL : OFF_BH) + r * ASTR + c * 16, g + r * 128 + c * 16);
    }
}
static __device__ __forceinline__ void load_f32split(unsigned char* sm, int oh, int ol,
        const float* base, const int* rows, int rbase, int koff, int tid) {
    for (int u = tid; u < 1024; u += 128) {
        int r = u >> 4, c4 = u & 15;
        size_t row = rows ? (size_t)rows[r] : (size_t)(rbase + r);
        float4 v = *(const float4*)(base + row * 128 + koff + c4 * 4);
        uint2 hi, lo;
        hi.x = prmt_hi16(__float_as_uint(v.x), __float_as_uint(v.y));
        hi.y = prmt_hi16(__float_as_uint(v.z), __float_as_uint(v.w));
        lo.x = bf2(v.y - trh(v.y), v.x - trh(v.x));
        lo.y = bf2(v.w - trh(v.w), v.z - trh(v.z));
        *(uint2*)(sm + oh + r * ASTR + c4 * 8) = hi;
        *(uint2*)(sm + ol + r * ASTR + c4 * 8) = lo;
    }
}

// ---- prep / CSR kernels ----
__global__ void prep_weights_kernel(const float* __restrict__ We1, const float* __restrict__ We2,
                                    const float* __restrict__ Wn1, const float* __restrict__ Wn2) {
    int s = blockIdx.x;
    const float* W; int slab;
    if (s < 6)       { W = We1; slab = s; }
    else if (s < 8)  { W = We2; slab = s - 6; }
    else if (s < 12) { W = Wn1; slab = s - 8; }
    else             { W = Wn2; slab = s - 12; }
    unsigned char* ph = g_Wh + s * 16384;
    unsigned char* pl = g_Wl + s * 16384;
    int k0 = slab * 64;
    for (int p = threadIdx.x; p < 4096; p += blockDim.x) {
        int n = p >> 5, kk = (p & 31) << 1;
        float x0 = W[(size_t)(k0 + kk) * 128 + n];
        float x1 = W[(size_t)(k0 + kk + 1) * 128 + n];
        *(uint32_t*)(ph + n * 128 + kk * 2) = prmt_hi16(__float_as_uint(x0), __float_as_uint(x1));
        *(uint32_t*)(pl + n * 128 + kk * 2) = bf2(x1 - trh(x1), x0 - trh(x0));
    }
}
__global__ void csr_zero_kernel() {
    int i = blockIdx.x * blockDim.x + threadIdx.x;
    if (i < NN) g_cnt[i] = 0;
}
__global__ void csr_hist_kernel(const int* __restrict__ dst) {
    int e = blockIdx.x * blockDim.x + threadIdx.x;
    if (e < NE) atomicAdd(&g_cnt[dst[e]], 1);
}
__global__ void csr_scan_kernel() {
    __shared__ int part[1024];
    const int t = threadIdx.x, CH = 49;
    int s0 = t * CH, s1 = s0 + CH;
    if (s0 > NN) s0 = NN;
    if (s1 > NN) s1 = NN;
    int s = 0;
    for (int i = s0; i < s1; i++) s += g_cnt[i];
    part[t] = s;
    __syncthreads();
    for (int d = 1; d < 1024; d <<= 1) {
        int v = (t >= d) ? part[t - d] : 0;
        __syncthreads();
        part[t] += v;
        __syncthreads();
    }
    int pre = (t == 0) ? 0 : part[t - 1];
    for (int i = s0; i < s1; i++) {
        g_off[i] = pre; g_cur[i] = pre;
        pre += g_cnt[i];
    }
    if (t == 1023) g_off[NN] = NE;
}
__global__ void csr_fill_kernel(const int* __restrict__ dst) {
    int e = blockIdx.x * blockDim.x + threadIdx.x;
    if (e < NE) {
        int pos = atomicAdd(&g_cur[dst[e]], 1);
        g_eord[pos] = e;
    }
}

// ---- precompute: U = nh@We1[0:128], V = nh@We1[128:256], P = nh@Wn1[128:256] ----
__global__ __launch_bounds__(128, 3)
void precompute_kernel(const float* __restrict__ node_h) {
    extern __shared__ __align__(1024) unsigned char sm[];
    const uint32_t sb = smem_u32(sm);
    const int tid = threadIdx.x, wid = tid >> 5, lane = tid & 31;
    const int nbase0 = blockIdx.x << 6;
    const int mrow = (wid >> 1) << 5;
    const int nbase = (wid & 1) << 6;

    int* rowsS = (int*)(sm + OFF_ROWS);
    if (tid < 64) { int n = nbase0 + tid; if (n >= NN) n = NN - 1; rowsS[tid] = n; }
    __syncthreads();

    load_f32split(sm, OFF_AH(0), OFF_AL(0), node_h, rowsS, 0, 0, tid);
    load_f32split(sm, OFF_AH(1), OFF_AL(1), node_h, rowsS, 0, 64, tid);
    __syncthreads();

    const int ra = mrow + (lane >> 2);
    const int cc = nbase + 2 * (lane & 3);
    const int w0[3] = {0, 2, 10}, w1[3] = {1, 3, 11};
    float* outs[3] = {g_U, g_V, g_P};
#pragma unroll 1
    for (int t = 0; t < 3; t++) {
        float acc[2][8][4]; ZACC(acc);
        load_W(sb, w0[t], tid); CPC(); CPW(0);
        __syncthreads();
        for (int c = 0; c < 4; c++)
            mma_chunk(sb + OFF_AH(0), sb + OFF_AL(0), ASTR, sb + OFF_BH, sb + OFF_BL,
                      mrow, nbase, c * 32, c * 32, lane, acc);
        __syncthreads();
        load_W(sb, w1[t], tid); CPC(); CPW(0);
        __syncthreads();
        for (int c = 0; c < 4; c++)
            mma_chunk(sb + OFF_AH(1), sb + OFF_AL(1), ASTR, sb + OFF_BH, sb + OFF_BL,
                      mrow, nbase, c * 32, c * 32, lane, acc);
        __syncthreads();
        float* op = outs[t];
#pragma unroll
        for (int mt = 0; mt < 2; mt++)
#pragma unroll
            for (int h = 0; h < 2; h++) {
                int r = ra + 16 * mt + 8 * h;
                int n = nbase0 + r;
                if (n < NN) {
#pragma unroll
                    for (int nt = 0; nt < 8; nt++) {
                        int c = cc + 8 * nt;
                        *(float2*)(op + (size_t)n * 128 + c) =
                            make_float2(acc[mt][nt][2 * h], acc[mt][nt][2 * h + 1]);
                    }
                }
            }
    }
}

// ---- edge kernel: GEMM1 = e@Wc, U/V in epilogue, y2 -> dense store ----
__global__ __launch_bounds__(128, 3)
void edge_kernel(const float* __restrict__ edge_h,
                 const int* __restrict__ src, const int* __restrict__ dst,
                 const float* __restrict__ be1) {
    extern __shared__ __align__(1024) unsigned char sm[];
    const uint32_t sb = smem_u32(sm);
    const int tid = threadIdx.x, wid = tid >> 5, lane = tid & 31;
    const int ebase = blockIdx.x << 6;
    const int mrow = (wid >> 1) << 5;
    const int nbase = (wid & 1) << 6;

    int* srcS = (int*)(sm + OFF_ROWS);
    int* dstS = (int*)(sm + OFF_DST);
    if (tid < 64) { srcS[tid] = src[ebase + tid]; dstS[tid] = dst[ebase + tid]; }

    load_W(sb, 4, tid); CPC();
    load_f32split(sm, OFF_AH(0), OFF_AL(0), edge_h, nullptr, ebase, 0, tid);
    load_f32split(sm, OFF_AH(1), OFF_AL(1), edge_h, nullptr, ebase, 64, tid);

    float acc[2][8][4]; ZACC(acc);
    CPW(0);
    __syncthreads();
    for (int c = 0; c < 4; c++)
        mma_chunk(sb + OFF_AH(0), sb + OFF_AL(0), ASTR, sb + OFF_BH, sb + OFF_BL,
                  mrow, nbase, c * 32, c * 32, lane, acc);
    __syncthreads();
    load_W(sb, 5, tid); CPC(); CPW(0);
    __syncthreads();
    for (int c = 0; c < 4; c++)
        mma_chunk(sb + OFF_AH(1), sb + OFF_AL(1), ASTR, sb + OFF_BH, sb + OFF_BL,
                  mrow, nbase, c * 32, c * 32, lane, acc);
    __syncthreads();
    load_W(sb, 6, tid); CPC();     // We2 k0 overlaps the epilogue

    // epilogue1: acc + U[src] + V[dst] + be1 -> relu -> split -> Y
    const int ra = mrow + (lane >> 2);
    const int cc = nbase + 2 * (lane & 3);
#pragma unroll
    for (int mt = 0; mt < 2; mt++)
#pragma unroll
        for (int h = 0; h < 2; h++) {
            int r = ra + 16 * mt + 8 * h;
            const float* up = g_U + (size_t)srcS[r] * 128;
            const float* vp = g_V + (size_t)dstS[r] * 128;
#pragma unroll
            for (int nt = 0; nt < 8; nt++) {
                int c = cc + 8 * nt;
                float2 u = __ldg((const float2*)(up + c));
                float2 v = __ldg((const float2*)(vp + c));
                float v0 = fmaxf(acc[mt][nt][2 * h]     + u.x + v.x + __ldg(&be1[c]),     0.f);
                float v1 = fmaxf(acc[mt][nt][2 * h + 1] + u.y + v.y + __ldg(&be1[c + 1]), 0.f);
                *(uint32_t*)(sm + OFF_AH(0) + r * YSTR + c * 2) =
                    prmt_hi16(__float_as_uint(v0), __float_as_uint(v1));
                *(uint32_t*)(sm + OFF_AL(0) + r * YSTR + c * 2) =
                    bf2(v1 - trh(v1), v0 - trh(v0));
            }
        }
    ZACC(acc);
    CPW(0);
    __syncthreads();
    for (int c = 0; c < 4; c++)
        mma_chunk(sb + OFF_AH(0), sb + OFF_AL(0), YSTR, sb + OFF_BH, sb + OFF_BL,
                  mrow, nbase, c * 32, c * 32, lane, acc);
    __syncthreads();
    load_W(sb, 7, tid); CPC(); CPW(0);
    __syncthreads();
    for (int c = 0; c < 4; c++)
        mma_chunk(sb + OFF_AH(0), sb + OFF_AL(0), YSTR, sb + OFF_BH, sb + OFF_BL,
                  mrow, nbase, (4 + c) * 32, c * 32, lane, acc);

    // epilogue2: dense y2 store (raw, no be2)
#pragma unroll
    for (int mt = 0; mt < 2; mt++)
#pragma unroll
        for (int h = 0; h < 2; h++) {
            int r = ra + 16 * mt + 8 * h;
            float* yp = g_y2 + (size_t)(ebase + r) * 128;
#pragma unroll
            for (int nt = 0; nt < 8; nt++) {
                int c = cc + 8 * nt;
                *(float2*)(yp + c) =
                    make_float2(acc[mt][nt][2 * h], acc[mt][nt][2 * h + 1]);
            }
        }
}

// ---- node kernel: CSR segment-sum of y2 + deg*be2, then node MLP ----
__global__ __launch_bounds__(128, 2)
void node_kernel(const float* __restrict__ be2,
                 const float* __restrict__ bn1, const float* __restrict__ bn2,
                 float* __restrict__ out) {
    extern __shared__ __align__(1024) unsigned char sm[];
    const uint32_t sb = smem_u32(sm);
    const int tid = threadIdx.x, wid = tid >> 5, lane = tid & 31;
    const int nbase0 = blockIdx.x << 6;
    const int mrow = (wid >> 1) << 5;
    const int nbase = (wid & 1) << 6;

    int* offS = (int*)(sm + OFF_ROWS);          // 65 ints
    int* eidS = (int*)(sm + SM_EIDS);           // EID_CAP ints
    if (tid < 65) { int n = nbase0 + tid; offS[tid] = g_off[n > NN ? NN : n]; }
    __syncthreads();
    const int base = offS[0];
    const int cnt = offS[64] - base;
    for (int u = tid; u < cnt && u < EID_CAP; u += 128) eidS[u] = g_eord[base + u];
    load_W(sb, 8, tid); CPC();
    __syncthreads();

    // aggregation: warp w handles rows w*16..w*16+15; lane owns cols 4*lane..+3
    const float4 b2 = __ldg((const float4*)(be2 + lane * 4));
    const int c0 = lane * 4, sl = c0 >> 6, k = c0 & 63;
#pragma unroll 1
    for (int i = 0; i < 16; i++) {
        int r = wid * 16 + i;
        int o0 = offS[r] - base, o1 = offS[r + 1] - base;
        float4 s = make_float4(0.f, 0.f, 0.f, 0.f);
        for (int j = o0; j < o1; j++) {
            int eid = (j < EID_CAP) ? eidS[j] : g_eord[base + j];
            float4 v = __ldg((const float4*)(g_y2 + (size_t)eid * 128 + c0));
            s.x += v.x; s.y += v.y; s.z += v.z; s.w += v.w;
        }
        float d = (float)(o1 - o0);
        s.x = fmaf(d, b2.x, s.x); s.y = fmaf(d, b2.y, s.y);
        s.z = fmaf(d, b2.z, s.z); s.w = fmaf(d, b2.w, s.w);
        uint2 hi, lo;
        hi.x = prmt_hi16(__float_as_uint(s.x), __float_as_uint(s.y));
        hi.y = prmt_hi16(__float_as_uint(s.z), __float_as_uint(s.w));
        lo.x = bf2(s.y - trh(s.y), s.x - trh(s.x));
        lo.y = bf2(s.w - trh(s.w), s.z - trh(s.z));
        *(uint2*)(sm + OFF_AH(sl) + r * ASTR + k * 2) = hi;
        *(uint2*)(sm + OFF_AL(sl) + r * ASTR + k * 2) = lo;
    }

    float acc[2][8][4]; ZACC(acc);
    CPW(0);
    __syncthreads();
    for (int c = 0; c < 4; c++)
        mma_chunk(sb + OFF_AH(0), sb + OFF_AL(0), ASTR, sb + OFF_BH, sb + OFF_BL,
                  mrow, nbase, c * 32, c * 32, lane, acc);
    __syncthreads();
    load_W(sb, 9, tid); CPC(); CPW(0);
    __syncthreads();
    for (int c = 0; c < 4; c++)
        mma_chunk(sb + OFF_AH(1), sb + OFF_AL(1), ASTR, sb + OFF_BH, sb + OFF_BL,
                  mrow, nbase, c * 32, c * 32, lane, acc);
    __syncthreads();
    load_W(sb, 12, tid); CPC();

    const int ra = mrow + (lane >> 2);
    const int cc = nbase + 2 * (lane & 3);
#pragma unroll
    for (int mt = 0; mt < 2; mt++)
#pragma unroll
        for (int h = 0; h < 2; h++) {
            int r = ra + 16 * mt + 8 * h;
            int n = nbase0 + r; if (n >= NN) n = NN - 1;
            const float* pp = g_P + (size_t)n * 128;
#pragma unroll
            for (int nt = 0; nt < 8; nt++) {
                int c = cc + 8 * nt;
                float2 p = __ldg((const float2*)(pp + c));
                float v0 = fmaxf(acc[mt][nt][2 * h]     + p.x + __ldg(&bn1[c]),     0.f);
                float v1 = fmaxf(acc[mt][nt][2 * h + 1] + p.y + __ldg(&bn1[c + 1]), 0.f);
                *(uint32_t*)(sm + OFF_AH(0) + r * YSTR + c * 2) =
                    prmt_hi16(__float_as_uint(v0), __float_as_uint(v1));
                *(uint32_t*)(sm + OFF_AL(0) + r * YSTR + c * 2) =
                    bf2(v1 - trh(v1), v0 - trh(v0));
            }
        }
    ZACC(acc);
    CPW(0);
    __syncthreads();
    for (int c = 0; c < 4; c++)
        mma_chunk(sb + OFF_AH(0), sb + OFF_AL(0), YSTR, sb + OFF_BH, sb + OFF_BL,
                  mrow, nbase, c * 32, c * 32, lane, acc);
    __syncthreads();
    load_W(sb, 13, tid); CPC(); CPW(0);
    __syncthreads();
    for (int c = 0; c < 4; c++)
        mma_chunk(sb + OFF_AH(0), sb + OFF_AL(0), YSTR, sb + OFF_BH, sb + OFF_BL,
                  mrow, nbase, (4 + c) * 32, c * 32, lane, acc);

#pragma unroll
    for (int mt = 0; mt < 2; mt++)
#pragma unroll
        for (int h = 0; h < 2; h++) {
            int r = ra + 16 * mt + 8 * h;
            int n = nbase0 + r;
            if (n < NN) {
#pragma unroll
                for (int nt = 0; nt < 8; nt++) {
                    int c = cc + 8 * nt;
                    *(float2*)(out + (size_t)n * 128 + c) =
                        make_float2(acc[mt][nt][2 * h]     + __ldg(&bn2[c]),
                                    acc[mt][nt][2 * h + 1] + __ldg(&bn2[c + 1]));
                }
            }
        }
}

extern "C" void kernel_launch(void* const* d_in, const int* in_sizes, int n_in,
                              void* d_out, int out_size) {
    const float* node_h = (const float*)d_in[0];
    const float* edge_h = (const float*)d_in[1];
    const int*   src    = (const int*)d_in[2];
    const int*   dst    = (const int*)d_in[3];
    const float* We1    = (const float*)d_in[4];
    const float* be1    = (const float*)d_in[5];
    const float* We2    = (const float*)d_in[6];
    const float* be2    = (const float*)d_in[7];
    const float* Wn1    = (const float*)d_in[8];
    const float* bn1    = (const float*)d_in[9];
    const float* Wn2    = (const float*)d_in[10];
    const float* bn2    = (const float*)d_in[11];
    float* out = (float*)d_out;

    cudaFuncSetAttribute(precompute_kernel, cudaFuncAttributeMaxDynamicSharedMemorySize, SM_BYTES);
    cudaFuncSetAttribute(edge_kernel, cudaFuncAttributeMaxDynamicSharedMemorySize, SM_BYTES);
    cudaFuncSetAttribute(node_kernel, cudaFuncAttributeMaxDynamicSharedMemorySize, SM_BYTES_NODE);

    prep_weights_kernel<<<14, 256>>>(We1, We2, Wn1, Wn2);
    csr_zero_kernel<<<(NN + 255) / 256, 256>>>();
    csr_hist_kernel<<<(NE + 255) / 256, 256>>>(dst);
    csr_scan_kernel<<<1, 1024>>>();
    csr_fill_kernel<<<(NE + 255) / 256, 256>>>(dst);
    precompute_kernel<<<(NN + 63) / 64, 128, SM_BYTES>>>(node_h);
    edge_kernel<<<NE / 64, 128, SM_BYTES>>>(edge_h, src, dst, be1);
    node_kernel<<<(NN + 63) / 64, 128, SM_BYTES_NODE>>>(be2, bn1, bn2, out);
}

// round 12
// speedup vs baseline: 1.4190x; 1.4190x over previous
#include <cuda_runtime.h>
#include <cstdint>

#define NN 50000
#define NE 640000

__device__ float g_agg[(size_t)NN * 128];
__device__ float g_U[(size_t)NN * 128];    // node_h @ We1[0:128]
__device__ float g_V[(size_t)NN * 128];    // node_h @ We1[128:256]
__device__ float g_P[(size_t)NN * 128];    // node_h @ Wn1[128:256]
// weight slab images, transposed [128 N x 64 K] bf16 row-major (128B/row):
// We1:0-5, We2:6-7, Wn1:8-11, Wn2:12-13
__device__ __align__(16) unsigned char g_Wh[14 * 16384];
__device__ __align__(16) unsigned char g_Wl[14 * 16384];

static __device__ __forceinline__ uint32_t smem_u32(const void* p) {
    uint32_t a;
    asm("{ .reg .u64 t; cvta.to.shared.u64 t, %1; cvt.u32.u64 %0, t; }" : "=r"(a) : "l"(p));
    return a;
}
static __device__ __forceinline__ uint32_t prmt_hi16(uint32_t a, uint32_t b) {
    uint32_t r; asm("prmt.b32 %0,%1,%2,0x7632;" : "=r"(r) : "r"(a), "r"(b)); return r;
}
static __device__ __forceinline__ float trh(float x) {
    return __uint_as_float(__float_as_uint(x) & 0xFFFF0000u);
}
static __device__ __forceinline__ uint32_t bf2(float hi_, float lo_) {
    uint32_t r; asm("cvt.rn.bf16x2.f32 %0,%1,%2;" : "=r"(r) : "f"(hi_), "f"(lo_)); return r;
}

#define CPA(dst, src) asm volatile("cp.async.ca.shared.global [%0], [%1], 16;" :: "r"(dst), "l"(src))
#define CPC()         asm volatile("cp.async.commit_group;" ::: "memory")
#define CPW(n)        asm volatile("cp.async.wait_group %0;" :: "n"(n) : "memory")

static __device__ __forceinline__ void ldsm4(uint32_t addr, uint32_t* r) {
    asm volatile("ldmatrix.sync.aligned.m8n8.x4.shared.b16 {%0,%1,%2,%3}, [%4];"
                 : "=r"(r[0]), "=r"(r[1]), "=r"(r[2]), "=r"(r[3]) : "r"(addr));
}
static __device__ __forceinline__ void mma16816(float* d, const uint32_t* a, const uint32_t* b) {
    asm volatile("mma.sync.aligned.m16n8k16.row.col.f32.bf16.bf16.f32 "
                 "{%0,%1,%2,%3},{%4,%5,%6,%7},{%8,%9},{%0,%1,%2,%3};"
                 : "+f"(d[0]), "+f"(d[1]), "+f"(d[2]), "+f"(d[3])
                 : "r"(a[0]), "r"(a[1]), "r"(a[2]), "r"(a[3]), "r"(b[0]), "r"(b[1]));
}

// SMEM: 64-row A tiles (hi/lo, double-buffered) + 128-row B (hi/lo, single)
#define OFF_DST  0
#define OFF_ROWS 256
#define ABUF     9216                     // 64 * 144
#define OFF_AH(b) (2048 + (b) * ABUF)     // AH0,AH1 contiguous (Y hi reuse)
#define OFF_AL(b) (2048 + 2 * ABUF + (b) * ABUF)
#define OFF_BH    (2048 + 4 * ABUF)       // 128 * 144 = 18432
#define OFF_BL    (OFF_BH + 18432)
#define SM_BYTES  (2048 + 4 * ABUF + 2 * 18432)   // 75776
#define ASTR 144
#define YSTR 272
#define YF   132    // fp32 staging stride (floats); 528B rows, 16B-aligned

#define ZACC(a) do {                                                   \
    _Pragma("unroll") for (int _m = 0; _m < 2; _m++)                   \
    _Pragma("unroll") for (int _n = 0; _n < 8; _n++)                   \
    _Pragma("unroll") for (int _q = 0; _q < 4; _q++) (a)[_m][_n][_q] = 0.f; } while (0)

// one K=16 chunk, 3-term compensated: 12 LDSM + 48 MMA (warp: 32 rows x 64 cols)
static __device__ __forceinline__ void mma_chunk(
        uint32_t ahb, uint32_t alb, int astride, uint32_t bhb, uint32_t blb,
        int mrow, int nbase, int kb, int bkb, int lane, float acc[2][8][4]) {
    uint32_t ah[2][4], al[2][4], bh[4][4], bl[4][4];
    const int arow = mrow + (lane & 15);
    const int ak   = kb + (lane >> 4) * 16;
#pragma unroll
    for (int mt = 0; mt < 2; mt++) {
        uint32_t off = (uint32_t)((arow + 16 * mt) * astride + ak);
        ldsm4(ahb + off, ah[mt]);
        ldsm4(alb + off, al[mt]);
    }
    const int bn = (lane & 7) + 8 * (lane >> 4);
    const int bk = bkb + ((lane >> 3) & 1) * 16;
#pragma unroll
    for (int nt2 = 0; nt2 < 4; nt2++) {
        uint32_t off = (uint32_t)((nbase + 16 * nt2 + bn) * ASTR + bk);
        ldsm4(bhb + off, bh[nt2]);
        ldsm4(blb + off, bl[nt2]);
    }
#pragma unroll
    for (int mt = 0; mt < 2; mt++)
#pragma unroll
        for (int nt = 0; nt < 8; nt++) {
            const uint32_t* bhp = &bh[nt >> 1][2 * (nt & 1)];
            const uint32_t* blp = &bl[nt >> 1][2 * (nt & 1)];
            mma16816(acc[mt][nt], ah[mt], bhp);
            mma16816(acc[mt][nt], ah[mt], blp);
            mma16816(acc[mt][nt], al[mt], bhp);
        }
}

// ---- loaders (128 threads) ----
static __device__ __forceinline__ void load_W(uint32_t sb, int slab, int tid) {
    for (int u = tid; u < 2048; u += 128) {
        int isLo = u >> 10, uu = u & 1023, r = uu >> 3, c = uu & 7;
        const unsigned char* g = (isLo ? g_Wl : g_Wh) + slab * 16384;
        CPA(sb + (isLo ? OFF_BL : OFF_BH) + r * ASTR + c * 16, g + r * 128 + c * 16);
    }
}
static __device__ __forceinline__ void load_f32split(unsigned char* sm, int oh, int ol,
        const float* base, const int* rows, int rbase, int koff, int tid) {
    for (int u = tid; u < 1024; u += 128) {
        int r = u >> 4, c4 = u & 15;
        size_t row = rows ? (size_t)rows[r] : (size_t)(rbase + r);
        float4 v = *(const float4*)(base + row * 128 + koff + c4 * 4);
        uint2 hi, lo;
        hi.x = prmt_hi16(__float_as_uint(v.x), __float_as_uint(v.y));
        hi.y = prmt_hi16(__float_as_uint(v.z), __float_as_uint(v.w));
        lo.x = bf2(v.y - trh(v.y), v.x - trh(v.x));
        lo.y = bf2(v.w - trh(v.w), v.z - trh(v.z));
        *(uint2*)(sm + oh + r * ASTR + c4 * 8) = hi;
        *(uint2*)(sm + ol + r * ASTR + c4 * 8) = lo;
    }
}

// ---- prep kernels ----
__global__ void zero_agg_kernel() {
    size_t stride = (size_t)gridDim.x * blockDim.x * 4;
    for (size_t i = (size_t)(blockIdx.x * blockDim.x + threadIdx.x) * 4;
         i < (size_t)NN * 128; i += stride)
        *(float4*)&g_agg[i] = make_float4(0.f, 0.f, 0.f, 0.f);
}
__global__ void prep_weights_kernel(const float* __restrict__ We1, const float* __restrict__ We2,
                                    const float* __restrict__ Wn1, const float* __restrict__ Wn2) {
    int s = blockIdx.x;
    const float* W; int slab;
    if (s < 6)       { W = We1; slab = s; }
    else if (s < 8)  { W = We2; slab = s - 6; }
    else if (s < 12) { W = Wn1; slab = s - 8; }
    else             { W = Wn2; slab = s - 12; }
    unsigned char* ph = g_Wh + s * 16384;
    unsigned char* pl = g_Wl + s * 16384;
    int k0 = slab * 64;
    for (int p = threadIdx.x; p < 4096; p += blockDim.x) {
        int n = p >> 5, kk = (p & 31) << 1;
        float x0 = W[(size_t)(k0 + kk) * 128 + n];
        float x1 = W[(size_t)(k0 + kk + 1) * 128 + n];
        *(uint32_t*)(ph + n * 128 + kk * 2) = prmt_hi16(__float_as_uint(x0), __float_as_uint(x1));
        *(uint32_t*)(pl + n * 128 + kk * 2) = bf2(x1 - trh(x1), x0 - trh(x0));
    }
}

// ---- precompute: U = nh@We1[0:128], V = nh@We1[128:256], P = nh@Wn1[128:256] ----
__global__ __launch_bounds__(128, 3)
void precompute_kernel(const float* __restrict__ node_h) {
    extern __shared__ __align__(1024) unsigned char sm[];
    const uint32_t sb = smem_u32(sm);
    const int tid = threadIdx.x, wid = tid >> 5, lane = tid & 31;
    const int nbase0 = blockIdx.x << 6;
    const int mrow = (wid >> 1) << 5;
    const int nbase = (wid & 1) << 6;

    int* rowsS = (int*)(sm + OFF_ROWS);
    if (tid < 64) { int n = nbase0 + tid; if (n >= NN) n = NN - 1; rowsS[tid] = n; }
    __syncthreads();

    load_f32split(sm, OFF_AH(0), OFF_AL(0), node_h, rowsS, 0, 0, tid);
    load_f32split(sm, OFF_AH(1), OFF_AL(1), node_h, rowsS, 0, 64, tid);
    __syncthreads();

    const int ra = mrow + (lane >> 2);
    const int cc = nbase + 2 * (lane & 3);
    const int w0[3] = {0, 2, 10}, w1[3] = {1, 3, 11};
    float* outs[3] = {g_U, g_V, g_P};
#pragma unroll 1
    for (int t = 0; t < 3; t++) {
        float acc[2][8][4]; ZACC(acc);
        load_W(sb, w0[t], tid); CPC(); CPW(0);
        __syncthreads();
        for (int c = 0; c < 4; c++)
            mma_chunk(sb + OFF_AH(0), sb + OFF_AL(0), ASTR, sb + OFF_BH, sb + OFF_BL,
                      mrow, nbase, c * 32, c * 32, lane, acc);
        __syncthreads();
        load_W(sb, w1[t], tid); CPC(); CPW(0);
        __syncthreads();
        for (int c = 0; c < 4; c++)
            mma_chunk(sb + OFF_AH(1), sb + OFF_AL(1), ASTR, sb + OFF_BH, sb + OFF_BL,
                      mrow, nbase, c * 32, c * 32, lane, acc);
        __syncthreads();
        float* op = outs[t];
#pragma unroll
        for (int mt = 0; mt < 2; mt++)
#pragma unroll
            for (int h = 0; h < 2; h++) {
                int r = ra + 16 * mt + 8 * h;
                int n = nbase0 + r;
                if (n < NN) {
#pragma unroll
                    for (int nt = 0; nt < 8; nt++) {
                        int c = cc + 8 * nt;
                        *(float2*)(op + (size_t)n * 128 + c) =
                            make_float2(acc[mt][nt][2 * h], acc[mt][nt][2 * h + 1]);
                    }
                }
            }
    }
}

// ---- edge kernel: GEMM1 = e@Wc, U/V in epilogue, v4-red scatter ----
__global__ __launch_bounds__(128, 3)
void edge_kernel(const float* __restrict__ edge_h,
                 const int* __restrict__ src, const int* __restrict__ dst,
                 const float* __restrict__ be1, const float* __restrict__ be2) {
    extern __shared__ __align__(1024) unsigned char sm[];
    const uint32_t sb = smem_u32(sm);
    const int tid = threadIdx.x, wid = tid >> 5, lane = tid & 31;
    const int ebase = blockIdx.x << 6;
    const int mrow = (wid >> 1) << 5;
    const int nbase = (wid & 1) << 6;

    int* srcS = (int*)(sm + OFF_ROWS);
    int* dstS = (int*)(sm + OFF_DST);
    if (tid < 64) { srcS[tid] = src[ebase + tid]; dstS[tid] = dst[ebase + tid]; }

    load_W(sb, 4, tid); CPC();
    load_f32split(sm, OFF_AH(0), OFF_AL(0), edge_h, nullptr, ebase, 0, tid);
    load_f32split(sm, OFF_AH(1), OFF_AL(1), edge_h, nullptr, ebase, 64, tid);

    float acc[2][8][4]; ZACC(acc);
    CPW(0);
    __syncthreads();
    for (int c = 0; c < 4; c++)
        mma_chunk(sb + OFF_AH(0), sb + OFF_AL(0), ASTR, sb + OFF_BH, sb + OFF_BL,
                  mrow, nbase, c * 32, c * 32, lane, acc);
    __syncthreads();
    load_W(sb, 5, tid); CPC(); CPW(0);
    __syncthreads();
    for (int c = 0; c < 4; c++)
        mma_chunk(sb + OFF_AH(1), sb + OFF_AL(1), ASTR, sb + OFF_BH, sb + OFF_BL,
                  mrow, nbase, c * 32, c * 32, lane, acc);
    __syncthreads();
    load_W(sb, 6, tid); CPC();     // We2 k0 overlaps the epilogue

    // epilogue1: acc + U[src] + V[dst] + be1 -> relu -> split -> Y
    const int ra = mrow + (lane >> 2);
    const int cc = nbase + 2 * (lane & 3);
#pragma unroll
    for (int mt = 0; mt < 2; mt++)
#pragma unroll
        for (int h = 0; h < 2; h++) {
            int r = ra + 16 * mt + 8 * h;
            const float* up = g_U + (size_t)srcS[r] * 128;
            const float* vp = g_V + (size_t)dstS[r] * 128;
#pragma unroll
            for (int nt = 0; nt < 8; nt++) {
                int c = cc + 8 * nt;
                float2 u = __ldg((const float2*)(up + c));
                float2 v = __ldg((const float2*)(vp + c));
                float v0 = fmaxf(acc[mt][nt][2 * h]     + u.x + v.x + __ldg(&be1[c]),     0.f);
                float v1 = fmaxf(acc[mt][nt][2 * h + 1] + u.y + v.y + __ldg(&be1[c + 1]), 0.f);
                *(uint32_t*)(sm + OFF_AH(0) + r * YSTR + c * 2) =
                    prmt_hi16(__float_as_uint(v0), __float_as_uint(v1));
                *(uint32_t*)(sm + OFF_AL(0) + r * YSTR + c * 2) =
                    bf2(v1 - trh(v1), v0 - trh(v0));
            }
        }
    ZACC(acc);
    CPW(0);
    __syncthreads();
    for (int c = 0; c < 4; c++)
        mma_chunk(sb + OFF_AH(0), sb + OFF_AL(0), YSTR, sb + OFF_BH, sb + OFF_BL,
                  mrow, nbase, c * 32, c * 32, lane, acc);
    __syncthreads();
    load_W(sb, 7, tid); CPC(); CPW(0);
    __syncthreads();
    for (int c = 0; c < 4; c++)
        mma_chunk(sb + OFF_AH(0), sb + OFF_AL(0), YSTR, sb + OFF_BH, sb + OFF_BL,
                  mrow, nbase, (4 + c) * 32, c * 32, lane, acc);
    __syncthreads();   // all warps done reading Y before staging overwrites it

    // epilogue2: stage y2 fp32 -> smem, then coalesced red.v4 scatter (+be2)
    float* stage = (float*)(sm + 2048);
#pragma unroll
    for (int mt = 0; mt < 2; mt++)
#pragma unroll
        for (int h = 0; h < 2; h++) {
            int r = ra + 16 * mt + 8 * h;
            float* row = stage + r * YF;
#pragma unroll
            for (int nt = 0; nt < 8; nt++) {
                int c = cc + 8 * nt;
                row[c]     = acc[mt][nt][2 * h];
                row[c + 1] = acc[mt][nt][2 * h + 1];
            }
        }
    __syncthreads();
    const float4 b2 = __ldg((const float4*)(be2 + lane * 4));
#pragma unroll 1
    for (int i = 0; i < 16; i++) {
        int r = wid * 16 + i;
        float4 v = *(const float4*)(stage + r * YF + lane * 4);
        v.x += b2.x; v.y += b2.y; v.z += b2.z; v.w += b2.w;
        float* gp = g_agg + (size_t)dstS[r] * 128 + lane * 4;
        asm volatile("red.global.add.v4.f32 [%0], {%1,%2,%3,%4};"
                     :: "l"(gp), "f"(v.x), "f"(v.y), "f"(v.z), "f"(v.w) : "memory");
    }
}

// ---- node kernel: GEMM1 = agg@Wn1[0:128] only, P in epilogue ----
__global__ __launch_bounds__(128, 3)
void node_kernel(const float* __restrict__ bn1, const float* __restrict__ bn2,
                 float* __restrict__ out) {
    extern __shared__ __align__(1024) unsigned char sm[];
    const uint32_t sb = smem_u32(sm);
    const int tid = threadIdx.x, wid = tid >> 5, lane = tid & 31;
    const int nbase0 = blockIdx.x << 6;
    const int mrow = (wid >> 1) << 5;
    const int nbase = (wid & 1) << 6;

    int* rowsS = (int*)(sm + OFF_ROWS);
    if (tid < 64) { int n = nbase0 + tid; if (n >= NN) n = NN - 1; rowsS[tid] = n; }
    __syncthreads();

    load_W(sb, 8, tid); CPC();
    load_f32split(sm, OFF_AH(0), OFF_AL(0), g_agg, rowsS, 0, 0, tid);
    load_f32split(sm, OFF_AH(1), OFF_AL(1), g_agg, rowsS, 0, 64, tid);

    float acc[2][8][4]; ZACC(acc);
    CPW(0);
    __syncthreads();
    for (int c = 0; c < 4; c++)
        mma_chunk(sb + OFF_AH(0), sb + OFF_AL(0), ASTR, sb + OFF_BH, sb + OFF_BL,
                  mrow, nbase, c * 32, c * 32, lane, acc);
    __syncthreads();
    load_W(sb, 9, tid); CPC(); CPW(0);
    __syncthreads();
    for (int c = 0; c < 4; c++)
        mma_chunk(sb + OFF_AH(1), sb + OFF_AL(1), ASTR, sb + OFF_BH, sb + OFF_BL,
                  mrow, nbase, c * 32, c * 32, lane, acc);
    __syncthreads();
    load_W(sb, 12, tid); CPC();

    const int ra = mrow + (lane >> 2);
    const int cc = nbase + 2 * (lane & 3);
#pragma unroll
    for (int mt = 0; mt < 2; mt++)
#pragma unroll
        for (int h = 0; h < 2; h++) {
            int r = ra + 16 * mt + 8 * h;
            int n = nbase0 + r; if (n >= NN) n = NN - 1;
            const float* pp = g_P + (size_t)n * 128;
#pragma unroll
            for (int nt = 0; nt < 8; nt++) {
                int c = cc + 8 * nt;
                float2 p = __ldg((const float2*)(pp + c));
                float v0 = fmaxf(acc[mt][nt][2 * h]     + p.x + __ldg(&bn1[c]),     0.f);
                float v1 = fmaxf(acc[mt][nt][2 * h + 1] + p.y + __ldg(&bn1[c + 1]), 0.f);
                *(uint32_t*)(sm + OFF_AH(0) + r * YSTR + c * 2) =
                    prmt_hi16(__float_as_uint(v0), __float_as_uint(v1));
                *(uint32_t*)(sm + OFF_AL(0) + r * YSTR + c * 2) =
                    bf2(v1 - trh(v1), v0 - trh(v0));
            }
        }
    ZACC(acc);
    CPW(0);
    __syncthreads();
    for (int c = 0; c < 4; c++)
        mma_chunk(sb + OFF_AH(0), sb + OFF_AL(0), YSTR, sb + OFF_BH, sb + OFF_BL,
                  mrow, nbase, c * 32, c * 32, lane, acc);
    __syncthreads();
    load_W(sb, 13, tid); CPC(); CPW(0);
    __syncthreads();
    for (int c = 0; c < 4; c++)
        mma_chunk(sb + OFF_AH(0), sb + OFF_AL(0), YSTR, sb + OFF_BH, sb + OFF_BL,
                  mrow, nbase, (4 + c) * 32, c * 32, lane, acc);

#pragma unroll
    for (int mt = 0; mt < 2; mt++)
#pragma unroll
        for (int h = 0; h < 2; h++) {
            int r = ra + 16 * mt + 8 * h;
            int n = nbase0 + r;
            if (n < NN) {
#pragma unroll
                for (int nt = 0; nt < 8; nt++) {
                    int c = cc + 8 * nt;
                    *(float2*)(out + (size_t)n * 128 + c) =
                        make_float2(acc[mt][nt][2 * h]     + __ldg(&bn2[c]),
                                    acc[mt][nt][2 * h + 1] + __ldg(&bn2[c + 1]));
                }
            }
        }
}

extern "C" void kernel_launch(void* const* d_in, const int* in_sizes, int n_in,
                              void* d_out, int out_size) {
    const float* node_h = (const float*)d_in[0];
    const float* edge_h = (const float*)d_in[1];
    const int*   src    = (const int*)d_in[2];
    const int*   dst    = (const int*)d_in[3];
    const float* We1    = (const float*)d_in[4];
    const float* be1    = (const float*)d_in[5];
    const float* We2    = (const float*)d_in[6];
    const float* be2    = (const float*)d_in[7];
    const float* Wn1    = (const float*)d_in[8];
    const float* bn1    = (const float*)d_in[9];
    const float* Wn2    = (const float*)d_in[10];
    const float* bn2    = (const float*)d_in[11];
    float* out = (float*)d_out;

    cudaFuncSetAttribute(precompute_kernel, cudaFuncAttributeMaxDynamicSharedMemorySize, SM_BYTES);
    cudaFuncSetAttribute(edge_kernel, cudaFuncAttributeMaxDynamicSharedMemorySize, SM_BYTES);
    cudaFuncSetAttribute(node_kernel, cudaFuncAttributeMaxDynamicSharedMemorySize, SM_BYTES);

    zero_agg_kernel<<<1024, 256>>>();
    prep_weights_kernel<<<14, 256>>>(We1, We2, Wn1, Wn2);
    precompute_kernel<<<(NN + 63) / 64, 128, SM_BYTES>>>(node_h);
    edge_kernel<<<NE / 64, 128, SM_BYTES>>>(edge_h, src, dst, be1, be2);
    node_kernel<<<(NN + 63) / 64, 128, SM_BYTES>>>(bn1, bn2, out);
}

// round 14
// speedup vs baseline: 1.7063x; 1.2025x over previous
#include <cuda_runtime.h>
#include <cuda_fp16.h>
#include <cstdint>

#define NN 50000
#define NE 640000

__device__ float g_agg[(size_t)NN * 128];
__device__ float g_U[(size_t)NN * 128];    // node_h @ We1[0:128]
__device__ float g_V[(size_t)NN * 128];    // node_h @ We1[128:256]
__device__ float g_P[(size_t)NN * 128];    // node_h @ Wn1[128:256]
// weight slab images (fp16 hi only), transposed [128 N x 64 K] row-major:
// We1:0-5, We2:6-7, Wn1:8-11, Wn2:12-13
__device__ __align__(16) unsigned char g_Wh[14 * 16384];

static __device__ __forceinline__ uint32_t smem_u32(const void* p) {
    uint32_t a;
    asm("{ .reg .u64 t; cvta.to.shared.u64 t, %1; cvt.u32.u64 %0, t; }" : "=r"(a) : "l"(p));
    return a;
}
// split pair (a=low element, b=high element) into fp16x2 hi + fp16x2 residual
static __device__ __forceinline__ void f16split(float a, float b, uint32_t& hi, uint32_t& lo) {
    __half2 h = __floats2half2_rn(a, b);
    float2 hf = __half22float2(h);
    __half2 l = __floats2half2_rn(a - hf.x, b - hf.y);
    hi = *reinterpret_cast<uint32_t*>(&h);
    lo = *reinterpret_cast<uint32_t*>(&l);
}

#define CPA(dst, src) asm volatile("cp.async.ca.shared.global [%0], [%1], 16;" :: "r"(dst), "l"(src))
#define CPC()         asm volatile("cp.async.commit_group;" ::: "memory")
#define CPW(n)        asm volatile("cp.async.wait_group %0;" :: "n"(n) : "memory")

static __device__ __forceinline__ void ldsm4(uint32_t addr, uint32_t* r) {
    asm volatile("ldmatrix.sync.aligned.m8n8.x4.shared.b16 {%0,%1,%2,%3}, [%4];"
                 : "=r"(r[0]), "=r"(r[1]), "=r"(r[2]), "=r"(r[3]) : "r"(addr));
}
static __device__ __forceinline__ void mma16816(float* d, const uint32_t* a, const uint32_t* b) {
    asm volatile("mma.sync.aligned.m16n8k16.row.col.f32.f16.f16.f32 "
                 "{%0,%1,%2,%3},{%4,%5,%6,%7},{%8,%9},{%0,%1,%2,%3};"
                 : "+f"(d[0]), "+f"(d[1]), "+f"(d[2]), "+f"(d[3])
                 : "r"(a[0]), "r"(a[1]), "r"(a[2]), "r"(a[3]), "r"(b[0]), "r"(b[1]));
}

// SMEM: 64-row A tiles (hi/lo, 2 slabs) + two resident 128-row B slabs (hi only)
#define OFF_DST  0
#define OFF_ROWS 256
#define ABUF     9216                     // 64 * 144
#define OFF_AH(b) (2048 + (b) * ABUF)     // AH0,AH1 contiguous (Y hi reuse)
#define OFF_AL(b) (2048 + 2 * ABUF + (b) * ABUF)
#define OFF_B(b)  (2048 + 4 * ABUF + (b) * 18432)
#define SM_BYTES  (2048 + 4 * ABUF + 2 * 18432)   // 75776
#define ASTR 144
#define YSTR 272
#define YF   132    // fp32 staging stride (floats)

#define ZACC(a) do {                                                   \
    _Pragma("unroll") for (int _m = 0; _m < 2; _m++)                   \
    _Pragma("unroll") for (int _n = 0; _n < 8; _n++)                   \
    _Pragma("unroll") for (int _q = 0; _q < 4; _q++) (a)[_m][_n][_q] = 0.f; } while (0)

// one K=16 chunk, 2-term compensated: 8 LDSM + 32 MMA (warp: 32 rows x 64 cols)
static __device__ __forceinline__ void mma_chunk(
        uint32_t ahb, uint32_t alb, int astride, uint32_t bb,
        int mrow, int nbase, int kb, int bkb, int lane, float acc[2][8][4]) {
    uint32_t ah[2][4], al[2][4], bh[4][4];
    const int arow = mrow + (lane & 15);
    const int ak   = kb + (lane >> 4) * 16;
#pragma unroll
    for (int mt = 0; mt < 2; mt++) {
        uint32_t off = (uint32_t)((arow + 16 * mt) * astride + ak);
        ldsm4(ahb + off, ah[mt]);
        ldsm4(alb + off, al[mt]);
    }
    const int bn = (lane & 7) + 8 * (lane >> 4);
    const int bk = bkb + ((lane >> 3) & 1) * 16;
#pragma unroll
    for (int nt2 = 0; nt2 < 4; nt2++)
        ldsm4(bb + (uint32_t)((nbase + 16 * nt2 + bn) * ASTR + bk), bh[nt2]);
#pragma unroll
    for (int mt = 0; mt < 2; mt++)
#pragma unroll
        for (int nt = 0; nt < 8; nt++) {
            const uint32_t* bhp = &bh[nt >> 1][2 * (nt & 1)];
            mma16816(acc[mt][nt], ah[mt], bhp);
            mma16816(acc[mt][nt], al[mt], bhp);
        }
}

// ---- loaders (128 threads) ----
static __device__ __forceinline__ void load_W(uint32_t sb, int boff, int slab, int tid) {
    for (int u = tid; u < 1024; u += 128) {
        int r = u >> 3, c = u & 7;
        CPA(sb + boff + r * ASTR + c * 16, g_Wh + slab * 16384 + r * 128 + c * 16);
    }
}
static __device__ __forceinline__ void load_f32split(unsigned char* sm, int oh, int ol,
        const float* base, const int* rows, int rbase, int koff, int tid) {
    for (int u = tid; u < 1024; u += 128) {
        int r = u >> 4, c4 = u & 15;
        size_t row = rows ? (size_t)rows[r] : (size_t)(rbase + r);
        float4 v = *(const float4*)(base + row * 128 + koff + c4 * 4);
        uint2 hi, lo;
        f16split(v.x, v.y, hi.x, lo.x);
        f16split(v.z, v.w, hi.y, lo.y);
        *(uint2*)(sm + oh + r * ASTR + c4 * 8) = hi;
        *(uint2*)(sm + ol + r * ASTR + c4 * 8) = lo;
    }
}

// ---- prep kernels ----
__global__ void zero_agg_kernel() {
    size_t stride = (size_t)gridDim.x * blockDim.x * 4;
    for (size_t i = (size_t)(blockIdx.x * blockDim.x + threadIdx.x) * 4;
         i < (size_t)NN * 128; i += stride)
        *(float4*)&g_agg[i] = make_float4(0.f, 0.f, 0.f, 0.f);
}
__global__ void prep_weights_kernel(const float* __restrict__ We1, const float* __restrict__ We2,
                                    const float* __restrict__ Wn1, const float* __restrict__ Wn2) {
    int s = blockIdx.x;
    const float* W; int slab;
    if (s < 6)       { W = We1; slab = s; }
    else if (s < 8)  { W = We2; slab = s - 6; }
    else if (s < 12) { W = Wn1; slab = s - 8; }
    else             { W = Wn2; slab = s - 12; }
    unsigned char* ph = g_Wh + s * 16384;
    int k0 = slab * 64;
    for (int p = threadIdx.x; p < 4096; p += blockDim.x) {
        int n = p >> 5, kk = (p & 31) << 1;
        float x0 = W[(size_t)(k0 + kk) * 128 + n];
        float x1 = W[(size_t)(k0 + kk + 1) * 128 + n];
        __half2 h = __floats2half2_rn(x0, x1);
        *(uint32_t*)(ph + n * 128 + kk * 2) = *reinterpret_cast<uint32_t*>(&h);
    }
}

// ---- precompute: U = nh@We1[0:128], V = nh@We1[128:256], P = nh@Wn1[128:256] ----
__global__ __launch_bounds__(128, 3)
void precompute_kernel(const float* __restrict__ node_h) {
    extern __shared__ __align__(1024) unsigned char sm[];
    const uint32_t sb = smem_u32(sm);
    const int tid = threadIdx.x, wid = tid >> 5, lane = tid & 31;
    const int nbase0 = blockIdx.x << 6;
    const int mrow = (wid >> 1) << 5;
    const int nbase = (wid & 1) << 6;

    int* rowsS = (int*)(sm + OFF_ROWS);
    if (tid < 64) { int n = nbase0 + tid; if (n >= NN) n = NN - 1; rowsS[tid] = n; }
    __syncthreads();

    load_f32split(sm, OFF_AH(0), OFF_AL(0), node_h, rowsS, 0, 0, tid);
    load_f32split(sm, OFF_AH(1), OFF_AL(1), node_h, rowsS, 0, 64, tid);
    __syncthreads();

    const int ra = mrow + (lane >> 2);
    const int cc = nbase + 2 * (lane & 3);
    const int w0[3] = {0, 2, 10}, w1[3] = {1, 3, 11};
    float* outs[3] = {g_U, g_V, g_P};
#pragma unroll 1
    for (int t = 0; t < 3; t++) {
        float acc[2][8][4]; ZACC(acc);
        load_W(sb, OFF_B(0), w0[t], tid);
        load_W(sb, OFF_B(1), w1[t], tid);
        CPC(); CPW(0);
        __syncthreads();
        for (int c = 0; c < 4; c++)
            mma_chunk(sb + OFF_AH(0), sb + OFF_AL(0), ASTR, sb + OFF_B(0),
                      mrow, nbase, c * 32, c * 32, lane, acc);
        for (int c = 0; c < 4; c++)
            mma_chunk(sb + OFF_AH(1), sb + OFF_AL(1), ASTR, sb + OFF_B(1),
                      mrow, nbase, c * 32, c * 32, lane, acc);
        __syncthreads();
        float* op = outs[t];
#pragma unroll
        for (int mt = 0; mt < 2; mt++)
#pragma unroll
            for (int h = 0; h < 2; h++) {
                int r = ra + 16 * mt + 8 * h;
                int n = nbase0 + r;
                if (n < NN) {
#pragma unroll
                    for (int nt = 0; nt < 8; nt++) {
                        int c = cc + 8 * nt;
                        *(float2*)(op + (size_t)n * 128 + c) =
                            make_float2(acc[mt][nt][2 * h], acc[mt][nt][2 * h + 1]);
                    }
                }
            }
    }
}

// ---- edge kernel: GEMM1 = e@Wc, U/V in epilogue, v4-red scatter ----
__global__ __launch_bounds__(128, 3)
void edge_kernel(const float* __restrict__ edge_h,
                 const int* __restrict__ src, const int* __restrict__ dst,
                 const float* __restrict__ be1, const float* __restrict__ be2) {
    extern __shared__ __align__(1024) unsigned char sm[];
    const uint32_t sb = smem_u32(sm);
    const int tid = threadIdx.x, wid = tid >> 5, lane = tid & 31;
    const int ebase = blockIdx.x << 6;
    const int mrow = (wid >> 1) << 5;
    const int nbase = (wid & 1) << 6;

    int* srcS = (int*)(sm + OFF_ROWS);
    int* dstS = (int*)(sm + OFF_DST);
    if (tid < 64) { srcS[tid] = src[ebase + tid]; dstS[tid] = dst[ebase + tid]; }

    load_W(sb, OFF_B(0), 4, tid);
    load_W(sb, OFF_B(1), 5, tid);
    CPC();
    load_f32split(sm, OFF_AH(0), OFF_AL(0), edge_h, nullptr, ebase, 0, tid);
    load_f32split(sm, OFF_AH(1), OFF_AL(1), edge_h, nullptr, ebase, 64, tid);

    float acc[2][8][4]; ZACC(acc);
    CPW(0);
    __syncthreads();
    for (int c = 0; c < 4; c++)
        mma_chunk(sb + OFF_AH(0), sb + OFF_AL(0), ASTR, sb + OFF_B(0),
                  mrow, nbase, c * 32, c * 32, lane, acc);
    __syncthreads();                       // B0 free
    load_W(sb, OFF_B(0), 6, tid); CPC();   // We2 k0 streams in during MMA
    for (int c = 0; c < 4; c++)
        mma_chunk(sb + OFF_AH(1), sb + OFF_AL(1), ASTR, sb + OFF_B(1),
                  mrow, nbase, c * 32, c * 32, lane, acc);
    __syncthreads();                       // B1 + A free
    load_W(sb, OFF_B(1), 7, tid); CPC();   // We2 k64 streams in during epilogue

    // epilogue1: acc + U[src] + V[dst] + be1 -> relu -> split -> Y
    const int ra = mrow + (lane >> 2);
    const int cc = nbase + 2 * (lane & 3);
#pragma unroll
    for (int mt = 0; mt < 2; mt++)
#pragma unroll
        for (int h = 0; h < 2; h++) {
            int r = ra + 16 * mt + 8 * h;
            const float* up = g_U + (size_t)srcS[r] * 128;
            const float* vp = g_V + (size_t)dstS[r] * 128;
#pragma unroll
            for (int nt = 0; nt < 8; nt++) {
                int c = cc + 8 * nt;
                float2 u = __ldg((const float2*)(up + c));
                float2 v = __ldg((const float2*)(vp + c));
                float v0 = fmaxf(acc[mt][nt][2 * h]     + u.x + v.x + __ldg(&be1[c]),     0.f);
                float v1 = fmaxf(acc[mt][nt][2 * h + 1] + u.y + v.y + __ldg(&be1[c + 1]), 0.f);
                uint32_t hv, lv;
                f16split(v0, v1, hv, lv);
                *(uint32_t*)(sm + OFF_AH(0) + r * YSTR + c * 2) = hv;
                *(uint32_t*)(sm + OFF_AL(0) + r * YSTR + c * 2) = lv;
            }
        }
    ZACC(acc);
    CPW(0);
    __syncthreads();
    // GEMM2: Y(K=128) @ We2, both slabs resident -> 8 chunks straight
    for (int c = 0; c < 8; c++)
        mma_chunk(sb + OFF_AH(0), sb + OFF_AL(0), YSTR, sb + OFF_B(c >> 2),
                  mrow, nbase, c * 32, (c & 3) * 32, lane, acc);
    __syncthreads();   // all warps done reading Y before staging overwrites it

    // epilogue2: stage y2 fp32 -> smem, then coalesced red.v4 scatter (+be2)
    float* stage = (float*)(sm + 2048);
#pragma unroll
    for (int mt = 0; mt < 2; mt++)
#pragma unroll
        for (int h = 0; h < 2; h++) {
            int r = ra + 16 * mt + 8 * h;
            float* row = stage + r * YF;
#pragma unroll
            for (int nt = 0; nt < 8; nt++) {
                int c = cc + 8 * nt;
                row[c]     = acc[mt][nt][2 * h];
                row[c + 1] = acc[mt][nt][2 * h + 1];
            }
        }
    __syncthreads();
    const float4 b2 = __ldg((const float4*)(be2 + lane * 4));
#pragma unroll 1
    for (int i = 0; i < 16; i++) {
        int r = wid * 16 + i;
        float4 v = *(const float4*)(stage + r * YF + lane * 4);
        v.x += b2.x; v.y += b2.y; v.z += b2.z; v.w += b2.w;
        float* gp = g_agg + (size_t)dstS[r] * 128 + lane * 4;
        asm volatile("red.global.add.v4.f32 [%0], {%1,%2,%3,%4};"
                     :: "l"(gp), "f"(v.x), "f"(v.y), "f"(v.z), "f"(v.w) : "memory");
    }
}

// ---- node kernel: GEMM1 = agg@Wn1[0:128] only, P in epilogue ----
__global__ __launch_bounds__(128, 3)
void node_kernel(const float* __restrict__ bn1, const float* __restrict__ bn2,
                 float* __restrict__ out) {
    extern __shared__ __align__(1024) unsigned char sm[];
    const uint32_t sb = smem_u32(sm);
    const int tid = threadIdx.x, wid = tid >> 5, lane = tid & 31;
    const int nbase0 = blockIdx.x << 6;
    const int mrow = (wid >> 1) << 5;
    const int nbase = (wid & 1) << 6;

    int* rowsS = (int*)(sm + OFF_ROWS);
    if (tid < 64) { int n = nbase0 + tid; if (n >= NN) n = NN - 1; rowsS[tid] = n; }
    __syncthreads();

    load_W(sb, OFF_B(0), 8, tid);
    load_W(sb, OFF_B(1), 9, tid);
    CPC();
    load_f32split(sm, OFF_AH(0), OFF_AL(0), g_agg, rowsS, 0, 0, tid);
    load_f32split(sm, OFF_AH(1), OFF_AL(1), g_agg, rowsS, 0, 64, tid);

    float acc[2][8][4]; ZACC(acc);
    CPW(0);
    __syncthreads();
    for (int c = 0; c < 4; c++)
        mma_chunk(sb + OFF_AH(0), sb + OFF_AL(0), ASTR, sb + OFF_B(0),
                  mrow, nbase, c * 32, c * 32, lane, acc);
    __syncthreads();
    load_W(sb, OFF_B(0), 12, tid); CPC();
    for (int c = 0; c < 4; c++)
        mma_chunk(sb + OFF_AH(1), sb + OFF_AL(1), ASTR, sb + OFF_B(1),
                  mrow, nbase, c * 32, c * 32, lane, acc);
    __syncthreads();
    load_W(sb, OFF_B(1), 13, tid); CPC();

    const int ra = mrow + (lane >> 2);
    const int cc = nbase + 2 * (lane & 3);
#pragma unroll
    for (int mt = 0; mt < 2; mt++)
#pragma unroll
        for (int h = 0; h < 2; h++) {
            int r = ra + 16 * mt + 8 * h;
            int n = nbase0 + r; if (n >= NN) n = NN - 1;
            const float* pp = g_P + (size_t)n * 128;
#pragma unroll
            for (int nt = 0; nt < 8; nt++) {
                int c = cc + 8 * nt;
                float2 p = __ldg((const float2*)(pp + c));
                float v0 = fmaxf(acc[mt][nt][2 * h]     + p.x + __ldg(&bn1[c]),     0.f);
                float v1 = fmaxf(acc[mt][nt][2 * h + 1] + p.y + __ldg(&bn1[c + 1]), 0.f);
                uint32_t hv, lv;
                f16split(v0, v1, hv, lv);
                *(uint32_t*)(sm + OFF_AH(0) + r * YSTR + c * 2) = hv;
                *(uint32_t*)(sm + OFF_AL(0) + r * YSTR + c * 2) = lv;
            }
        }
    ZACC(acc);
    CPW(0);
    __syncthreads();
    for (int c = 0; c < 8; c++)
        mma_chunk(sb + OFF_AH(0), sb + OFF_AL(0), YSTR, sb + OFF_B(c >> 2),
                  mrow, nbase, c * 32, (c & 3) * 32, lane, acc);

#pragma unroll
    for (int mt = 0; mt < 2; mt++)
#pragma unroll
        for (int h = 0; h < 2; h++) {
            int r = ra + 16 * mt + 8 * h;
            int n = nbase0 + r;
            if (n < NN) {
#pragma unroll
                for (int nt = 0; nt < 8; nt++) {
                    int c = cc + 8 * nt;
                    *(float2*)(out + (size_t)n * 128 + c) =
                        make_float2(acc[mt][nt][2 * h]     + __ldg(&bn2[c]),
                                    acc[mt][nt][2 * h + 1] + __ldg(&bn2[c + 1]));
                }
            }
        }
}

extern "C" void kernel_launch(void* const* d_in, const int* in_sizes, int n_in,
                              void* d_out, int out_size) {
    const float* node_h = (const float*)d_in[0];
    const float* edge_h = (const float*)d_in[1];
    const int*   src    = (const int*)d_in[2];
    const int*   dst    = (const int*)d_in[3];
    const float* We1    = (const float*)d_in[4];
    const float* be1    = (const float*)d_in[5];
    const float* We2    = (const float*)d_in[6];
    const float* be2    = (const float*)d_in[7];
    const float* Wn1    = (const float*)d_in[8];
    const float* bn1    = (const float*)d_in[9];
    const float* Wn2    = (const float*)d_in[10];
    const float* bn2    = (const float*)d_in[11];
    float* out = (float*)d_out;

    cudaFuncSetAttribute(precompute_kernel, cudaFuncAttributeMaxDynamicSharedMemorySize, SM_BYTES);
    cudaFuncSetAttribute(edge_kernel, cudaFuncAttributeMaxDynamicSharedMemorySize, SM_BYTES);
    cudaFuncSetAttribute(node_kernel, cudaFuncAttributeMaxDynamicSharedMemorySize, SM_BYTES);

    zero_agg_kernel<<<1024, 256>>>();
    prep_weights_kernel<<<14, 256>>>(We1, We2, Wn1, Wn2);
    precompute_kernel<<<(NN + 63) / 64, 128, SM_BYTES>>>(node_h);
    edge_kernel<<<NE / 64, 128, SM_BYTES>>>(edge_h, src, dst, be1, be2);
    node_kernel<<<(NN + 63) / 64, 128, SM_BYTES>>>(bn1, bn2, out);
}

// round 16
// speedup vs baseline: 1.9127x; 1.1210x over previous
#include <cuda_runtime.h>
#include <cuda_fp16.h>
#include <cstdint>

#define NN 50000
#define NE 640000

__device__ float g_agg[(size_t)NN * 128];
__device__ float g_U[(size_t)NN * 128];    // node_h @ We1[0:128]
__device__ float g_V[(size_t)NN * 128];    // node_h @ We1[128:256]
__device__ float g_P[(size_t)NN * 128];    // node_h @ Wn1[128:256]
// weight slab images (fp16), transposed [128 N x 64 K] row-major:
// We1:0-5, We2:6-7, Wn1:8-11, Wn2:12-13
__device__ __align__(16) unsigned char g_Wh[14 * 16384];

static __device__ __forceinline__ uint32_t smem_u32(const void* p) {
    uint32_t a;
    asm("{ .reg .u64 t; cvta.to.shared.u64 t, %1; cvt.u32.u64 %0, t; }" : "=r"(a) : "l"(p));
    return a;
}
static __device__ __forceinline__ void f16split(float a, float b, uint32_t& hi, uint32_t& lo) {
    __half2 h = __floats2half2_rn(a, b);
    float2 hf = __half22float2(h);
    __half2 l = __floats2half2_rn(a - hf.x, b - hf.y);
    hi = *reinterpret_cast<uint32_t*>(&h);
    lo = *reinterpret_cast<uint32_t*>(&l);
}

#define CPA(dst, src) asm volatile("cp.async.ca.shared.global [%0], [%1], 16;" :: "r"(dst), "l"(src))
#define CPC()         asm volatile("cp.async.commit_group;" ::: "memory")
#define CPW(n)        asm volatile("cp.async.wait_group %0;" :: "n"(n) : "memory")

static __device__ __forceinline__ void ldsm4(uint32_t addr, uint32_t* r) {
    asm volatile("ldmatrix.sync.aligned.m8n8.x4.shared.b16 {%0,%1,%2,%3}, [%4];"
                 : "=r"(r[0]), "=r"(r[1]), "=r"(r[2]), "=r"(r[3]) : "r"(addr));
}
static __device__ __forceinline__ void mma16816(float* d, const uint32_t* a, const uint32_t* b) {
    asm volatile("mma.sync.aligned.m16n8k16.row.col.f32.f16.f16.f32 "
                 "{%0,%1,%2,%3},{%4,%5,%6,%7},{%8,%9},{%0,%1,%2,%3};"
                 : "+f"(d[0]), "+f"(d[1]), "+f"(d[2]), "+f"(d[3])
                 : "r"(a[0]), "r"(a[1]), "r"(a[2]), "r"(a[3]), "r"(b[0]), "r"(b[1]));
}

// SMEM (56320 B -> 4 CTAs/SM): header 1KB | A hi/lo x2 slabs | single B slab
#define OFF_DST  0
#define OFF_ROWS 256
#define ABUF     9216                     // 64 * 144
#define OFF_AH(b) (1024 + (b) * ABUF)     // AH0,AH1 contiguous (Y hi reuse)
#define OFF_AL(b) (1024 + 2 * ABUF + (b) * ABUF)
#define OFF_B     (1024 + 4 * ABUF)       // 128 * 144 = 18432
#define SM_BYTES  (1024 + 4 * ABUF + 18432)   // 56320
#define ASTR 144
#define YSTR 272
#define YF   132    // fp32 staging stride (floats)

#define ZACC(a) do {                                                   \
    _Pragma("unroll") for (int _m = 0; _m < 2; _m++)                   \
    _Pragma("unroll") for (int _n = 0; _n < 8; _n++)                   \
    _Pragma("unroll") for (int _q = 0; _q < 4; _q++) (a)[_m][_n][_q] = 0.f; } while (0)

// one K=16 chunk, 2-term compensated: 8 LDSM + 32 MMA (warp: 32 rows x 64 cols)
// B fragments loaded per-nt2 pair to keep live regs under the 128 ceiling.
static __device__ __forceinline__ void mma_chunk(
        uint32_t ahb, uint32_t alb, int astride, uint32_t bb,
        int mrow, int nbase, int kb, int bkb, int lane, float acc[2][8][4]) {
    uint32_t ah[2][4], al[2][4];
    const int arow = mrow + (lane & 15);
    const int ak   = kb + (lane >> 4) * 16;
#pragma unroll
    for (int mt = 0; mt < 2; mt++) {
        uint32_t off = (uint32_t)((arow + 16 * mt) * astride + ak);
        ldsm4(ahb + off, ah[mt]);
        ldsm4(alb + off, al[mt]);
    }
    const int bn = (lane & 7) + 8 * (lane >> 4);
    const int bk = bkb + ((lane >> 3) & 1) * 16;
#pragma unroll
    for (int nt2 = 0; nt2 < 4; nt2++) {
        uint32_t bh[4];
        ldsm4(bb + (uint32_t)((nbase + 16 * nt2 + bn) * ASTR + bk), bh);
#pragma unroll
        for (int half = 0; half < 2; half++) {
            int nt = 2 * nt2 + half;
            const uint32_t* bhp = &bh[2 * half];
#pragma unroll
            for (int mt = 0; mt < 2; mt++) {
                mma16816(acc[mt][nt], ah[mt], bhp);
                mma16816(acc[mt][nt], al[mt], bhp);
            }
        }
    }
}

// ---- loaders (128 threads) ----
static __device__ __forceinline__ void load_W(uint32_t sb, int slab, int tid) {
    for (int u = tid; u < 1024; u += 128) {
        int r = u >> 3, c = u & 7;
        CPA(sb + OFF_B + r * ASTR + c * 16, g_Wh + slab * 16384 + r * 128 + c * 16);
    }
}
static __device__ __forceinline__ void load_f32split(unsigned char* sm, int oh, int ol,
        const float* base, const int* rows, int rbase, int koff, int tid) {
    for (int u = tid; u < 1024; u += 128) {
        int r = u >> 4, c4 = u & 15;
        size_t row = rows ? (size_t)rows[r] : (size_t)(rbase + r);
        float4 v = *(const float4*)(base + row * 128 + koff + c4 * 4);
        uint2 hi, lo;
        f16split(v.x, v.y, hi.x, lo.x);
        f16split(v.z, v.w, hi.y, lo.y);
        *(uint2*)(sm + oh + r * ASTR + c4 * 8) = hi;
        *(uint2*)(sm + ol + r * ASTR + c4 * 8) = lo;
    }
}

// ---- prep kernels ----
__global__ void zero_agg_kernel() {
    size_t stride = (size_t)gridDim.x * blockDim.x * 4;
    for (size_t i = (size_t)(blockIdx.x * blockDim.x + threadIdx.x) * 4;
         i < (size_t)NN * 128; i += stride)
        *(float4*)&g_agg[i] = make_float4(0.f, 0.f, 0.f, 0.f);
}
__global__ void prep_weights_kernel(const float* __restrict__ We1, const float* __restrict__ We2,
                                    const float* __restrict__ Wn1, const float* __restrict__ Wn2) {
    int s = blockIdx.x;
    const float* W; int slab;
    if (s < 6)       { W = We1; slab = s; }
    else if (s < 8)  { W = We2; slab = s - 6; }
    else if (s < 12) { W = Wn1; slab = s - 8; }
    else             { W = Wn2; slab = s - 12; }
    unsigned char* ph = g_Wh + s * 16384;
    int k0 = slab * 64;
    for (int p = threadIdx.x; p < 4096; p += blockDim.x) {
        int n = p >> 5, kk = (p & 31) << 1;
        float x0 = W[(size_t)(k0 + kk) * 128 + n];
        float x1 = W[(size_t)(k0 + kk + 1) * 128 + n];
        __half2 h = __floats2half2_rn(x0, x1);
        *(uint32_t*)(ph + n * 128 + kk * 2) = *reinterpret_cast<uint32_t*>(&h);
    }
}

// ---- precompute: U = nh@We1[0:128], V = nh@We1[128:256], P = nh@Wn1[128:256] ----
__global__ __launch_bounds__(128, 4)
void precompute_kernel(const float* __restrict__ node_h) {
    extern __shared__ __align__(1024) unsigned char sm[];
    const uint32_t sb = smem_u32(sm);
    const int tid = threadIdx.x, wid = tid >> 5, lane = tid & 31;
    const int nbase0 = blockIdx.x << 6;
    const int mrow = (wid >> 1) << 5;
    const int nbase = (wid & 1) << 6;

    int* rowsS = (int*)(sm + OFF_ROWS);
    if (tid < 64) { int n = nbase0 + tid; if (n >= NN) n = NN - 1; rowsS[tid] = n; }
    __syncthreads();

    load_f32split(sm, OFF_AH(0), OFF_AL(0), node_h, rowsS, 0, 0, tid);
    load_f32split(sm, OFF_AH(1), OFF_AL(1), node_h, rowsS, 0, 64, tid);
    __syncthreads();

    const int ra = mrow + (lane >> 2);
    const int cc = nbase + 2 * (lane & 3);
    const int w0[3] = {0, 2, 10}, w1[3] = {1, 3, 11};
    float* outs[3] = {g_U, g_V, g_P};
#pragma unroll 1
    for (int t = 0; t < 3; t++) {
        float acc[2][8][4]; ZACC(acc);
        load_W(sb, w0[t], tid); CPC(); CPW(0);
        __syncthreads();
        for (int c = 0; c < 4; c++)
            mma_chunk(sb + OFF_AH(0), sb + OFF_AL(0), ASTR, sb + OFF_B,
                      mrow, nbase, c * 32, c * 32, lane, acc);
        __syncthreads();
        load_W(sb, w1[t], tid); CPC(); CPW(0);
        __syncthreads();
        for (int c = 0; c < 4; c++)
            mma_chunk(sb + OFF_AH(1), sb + OFF_AL(1), ASTR, sb + OFF_B,
                      mrow, nbase, c * 32, c * 32, lane, acc);
        __syncthreads();
        float* op = outs[t];
#pragma unroll
        for (int mt = 0; mt < 2; mt++)
#pragma unroll
            for (int h = 0; h < 2; h++) {
                int r = ra + 16 * mt + 8 * h;
                int n = nbase0 + r;
                if (n < NN) {
#pragma unroll
                    for (int nt = 0; nt < 8; nt++) {
                        int c = cc + 8 * nt;
                        *(float2*)(op + (size_t)n * 128 + c) =
                            make_float2(acc[mt][nt][2 * h], acc[mt][nt][2 * h + 1]);
                    }
                }
            }
    }
}

// ---- edge kernel: GEMM1 = e@Wc, U/V in epilogue, v4-red scatter ----
__global__ __launch_bounds__(128, 4)
void edge_kernel(const float* __restrict__ edge_h,
                 const int* __restrict__ src, const int* __restrict__ dst,
                 const float* __restrict__ be1, const float* __restrict__ be2) {
    extern __shared__ __align__(1024) unsigned char sm[];
    const uint32_t sb = smem_u32(sm);
    const int tid = threadIdx.x, wid = tid >> 5, lane = tid & 31;
    const int ebase = blockIdx.x << 6;
    const int mrow = (wid >> 1) << 5;
    const int nbase = (wid & 1) << 6;

    int* srcS = (int*)(sm + OFF_ROWS);
    int* dstS = (int*)(sm + OFF_DST);
    if (tid < 64) { srcS[tid] = src[ebase + tid]; dstS[tid] = dst[ebase + tid]; }

    load_W(sb, 4, tid); CPC();
    load_f32split(sm, OFF_AH(0), OFF_AL(0), edge_h, nullptr, ebase, 0, tid);
    load_f32split(sm, OFF_AH(1), OFF_AL(1), edge_h, nullptr, ebase, 64, tid);

    float acc[2][8][4]; ZACC(acc);
    CPW(0);
    __syncthreads();
    for (int c = 0; c < 4; c++)
        mma_chunk(sb + OFF_AH(0), sb + OFF_AL(0), ASTR, sb + OFF_B,
                  mrow, nbase, c * 32, c * 32, lane, acc);
    __syncthreads();                       // B free
    load_W(sb, 5, tid); CPC(); CPW(0);
    __syncthreads();
    for (int c = 0; c < 4; c++)
        mma_chunk(sb + OFF_AH(1), sb + OFF_AL(1), ASTR, sb + OFF_B,
                  mrow, nbase, c * 32, c * 32, lane, acc);
    __syncthreads();                       // B + A free
    load_W(sb, 6, tid); CPC();             // We2 k0 streams in during epilogue

    // epilogue1: acc + U[src] + V[dst] + be1 -> relu -> split -> Y
    const int ra = mrow + (lane >> 2);
    const int cc = nbase + 2 * (lane & 3);
#pragma unroll
    for (int mt = 0; mt < 2; mt++)
#pragma unroll
        for (int h = 0; h < 2; h++) {
            int r = ra + 16 * mt + 8 * h;
            const float* up = g_U + (size_t)srcS[r] * 128;
            const float* vp = g_V + (size_t)dstS[r] * 128;
#pragma unroll
            for (int nt = 0; nt < 8; nt++) {
                int c = cc + 8 * nt;
                float2 u = __ldg((const float2*)(up + c));
                float2 v = __ldg((const float2*)(vp + c));
                float v0 = fmaxf(acc[mt][nt][2 * h]     + u.x + v.x + __ldg(&be1[c]),     0.f);
                float v1 = fmaxf(acc[mt][nt][2 * h + 1] + u.y + v.y + __ldg(&be1[c + 1]), 0.f);
                uint32_t hv, lv;
                f16split(v0, v1, hv, lv);
                *(uint32_t*)(sm + OFF_AH(0) + r * YSTR + c * 2) = hv;
                *(uint32_t*)(sm + OFF_AL(0) + r * YSTR + c * 2) = lv;
            }
        }
    ZACC(acc);
    CPW(0);
    __syncthreads();
    // GEMM2 part 1: Y @ We2 k0
    for (int c = 0; c < 4; c++)
        mma_chunk(sb + OFF_AH(0), sb + OFF_AL(0), YSTR, sb + OFF_B,
                  mrow, nbase, c * 32, c * 32, lane, acc);
    __syncthreads();
    load_W(sb, 7, tid); CPC(); CPW(0);
    __syncthreads();
    // GEMM2 part 2: Y @ We2 k64
    for (int c = 0; c < 4; c++)
        mma_chunk(sb + OFF_AH(0), sb + OFF_AL(0), YSTR, sb + OFF_B,
                  mrow, nbase, (4 + c) * 32, c * 32, lane, acc);
    __syncthreads();   // all warps done reading Y before staging overwrites it

    // epilogue2: stage y2 fp32 -> smem, then coalesced red.v4 scatter (+be2)
    float* stage = (float*)(sm + 1024);
#pragma unroll
    for (int mt = 0; mt < 2; mt++)
#pragma unroll
        for (int h = 0; h < 2; h++) {
            int r = ra + 16 * mt + 8 * h;
            float* row = stage + r * YF;
#pragma unroll
            for (int nt = 0; nt < 8; nt++) {
                int c = cc + 8 * nt;
                row[c]     = acc[mt][nt][2 * h];
                row[c + 1] = acc[mt][nt][2 * h + 1];
            }
        }
    __syncthreads();
    const float4 b2 = __ldg((const float4*)(be2 + lane * 4));
#pragma unroll 1
    for (int i = 0; i < 16; i++) {
        int r = wid * 16 + i;
        float4 v = *(const float4*)(stage + r * YF + lane * 4);
        v.x += b2.x; v.y += b2.y; v.z += b2.z; v.w += b2.w;
        float* gp = g_agg + (size_t)dstS[r] * 128 + lane * 4;
        asm volatile("red.global.add.v4.f32 [%0], {%1,%2,%3,%4};"
                     :: "l"(gp), "f"(v.x), "f"(v.y), "f"(v.z), "f"(v.w) : "memory");
    }
}

// ---- node kernel: GEMM1 = agg@Wn1[0:128] only, P in epilogue ----
__global__ __launch_bounds__(128, 4)
void node_kernel(const float* __restrict__ bn1, const float* __restrict__ bn2,
                 float* __restrict__ out) {
    extern __shared__ __align__(1024) unsigned char sm[];
    const uint32_t sb = smem_u32(sm);
    const int tid = threadIdx.x, wid = tid >> 5, lane = tid & 31;
    const int nbase0 = blockIdx.x << 6;
    const int mrow = (wid >> 1) << 5;
    const int nbase = (wid & 1) << 6;

    int* rowsS = (int*)(sm + OFF_ROWS);
    if (tid < 64) { int n = nbase0 + tid; if (n >= NN) n = NN - 1; rowsS[tid] = n; }
    __syncthreads();

    load_W(sb, 8, tid); CPC();
    load_f32split(sm, OFF_AH(0), OFF_AL(0), g_agg, rowsS, 0, 0, tid);
    load_f32split(sm, OFF_AH(1), OFF_AL(1), g_agg, rowsS, 0, 64, tid);

    float acc[2][8][4]; ZACC(acc);
    CPW(0);
    __syncthreads();
    for (int c = 0; c < 4; c++)
        mma_chunk(sb + OFF_AH(0), sb + OFF_AL(0), ASTR, sb + OFF_B,
                  mrow, nbase, c * 32, c * 32, lane, acc);
    __syncthreads();
    load_W(sb, 9, tid); CPC(); CPW(0);
    __syncthreads();
    for (int c = 0; c < 4; c++)
        mma_chunk(sb + OFF_AH(1), sb + OFF_AL(1), ASTR, sb + OFF_B,
                  mrow, nbase, c * 32, c * 32, lane, acc);
    __syncthreads();
    load_W(sb, 12, tid); CPC();

    const int ra = mrow + (lane >> 2);
    const int cc = nbase + 2 * (lane & 3);
#pragma unroll
    for (int mt = 0; mt < 2; mt++)
#pragma unroll
        for (int h = 0; h < 2; h++) {
            int r = ra + 16 * mt + 8 * h;
            int n = nbase0 + r; if (n >= NN) n = NN - 1;
            const float* pp = g_P + (size_t)n * 128;
#pragma unroll
            for (int nt = 0; nt < 8; nt++) {
                int c = cc + 8 * nt;
                float2 p = __ldg((const float2*)(pp + c));
                float v0 = fmaxf(acc[mt][nt][2 * h]     + p.x + __ldg(&bn1[c]),     0.f);
                float v1 = fmaxf(acc[mt][nt][2 * h + 1] + p.y + __ldg(&bn1[c + 1]), 0.f);
                uint32_t hv, lv;
                f16split(v0, v1, hv, lv);
                *(uint32_t*)(sm + OFF_AH(0) + r * YSTR + c * 2) = hv;
                *(uint32_t*)(sm + OFF_AL(0) + r * YSTR + c * 2) = lv;
            }
        }
    ZACC(acc);
    CPW(0);
    __syncthreads();
    for (int c = 0; c < 4; c++)
        mma_chunk(sb + OFF_AH(0), sb + OFF_AL(0), YSTR, sb + OFF_B,
                  mrow, nbase, c * 32, c * 32, lane, acc);
    __syncthreads();
    load_W(sb, 13, tid); CPC(); CPW(0);
    __syncthreads();
    for (int c = 0; c < 4; c++)
        mma_chunk(sb + OFF_AH(0), sb + OFF_AL(0), YSTR, sb + OFF_B,
                  mrow, nbase, (4 + c) * 32, c * 32, lane, acc);

#pragma unroll
    for (int mt = 0; mt < 2; mt++)
#pragma unroll
        for (int h = 0; h < 2; h++) {
            int r = ra + 16 * mt + 8 * h;
            int n = nbase0 + r;
            if (n < NN) {
#pragma unroll
                for (int nt = 0; nt < 8; nt++) {
                    int c = cc + 8 * nt;
                    *(float2*)(out + (size_t)n * 128 + c) =
                        make_float2(acc[mt][nt][2 * h]     + __ldg(&bn2[c]),
                                    acc[mt][nt][2 * h + 1] + __ldg(&bn2[c + 1]));
                }
            }
        }
}

extern "C" void kernel_launch(void* const* d_in, const int* in_sizes, int n_in,
                              void* d_out, int out_size) {
    const float* node_h = (const float*)d_in[0];
    const float* edge_h = (const float*)d_in[1];
    const int*   src    = (const int*)d_in[2];
    const int*   dst    = (const int*)d_in[3];
    const float* We1    = (const float*)d_in[4];
    const float* be1    = (const float*)d_in[5];
    const float* We2    = (const float*)d_in[6];
    const float* be2    = (const float*)d_in[7];
    const float* Wn1    = (const float*)d_in[8];
    const float* bn1    = (const float*)d_in[9];
    const float* Wn2    = (const float*)d_in[10];
    const float* bn2    = (const float*)d_in[11];
    float* out = (float*)d_out;

    cudaFuncSetAttribute(precompute_kernel, cudaFuncAttributeMaxDynamicSharedMemorySize, SM_BYTES);
    cudaFuncSetAttribute(edge_kernel, cudaFuncAttributeMaxDynamicSharedMemorySize, SM_BYTES);
    cudaFuncSetAttribute(node_kernel, cudaFuncAttributeMaxDynamicSharedMemorySize, SM_BYTES);

    zero_agg_kernel<<<1024, 256>>>();
    prep_weights_kernel<<<14, 256>>>(We1, We2, Wn1, Wn2);
    precompute_kernel<<<(NN + 63) / 64, 128, SM_BYTES>>>(node_h);
    edge_kernel<<<NE / 64, 128, SM_BYTES>>>(edge_h, src, dst, be1, be2);
    node_kernel<<<(NN + 63) / 64, 128, SM_BYTES>>>(bn1, bn2, out);
}

// round 17
// speedup vs baseline: 2.2267x; 1.1642x over previous
#include <cuda_runtime.h>
#include <cuda_fp16.h>
#include <cstdint>

#define NN 50000
#define NE 640000

__device__ float g_agg[(size_t)NN * 128];
__device__ float g_U[(size_t)NN * 128];    // node_h @ We1[0:128]
__device__ float g_V[(size_t)NN * 128];    // node_h @ We1[128:256] + be1
__device__ float g_P[(size_t)NN * 128];    // node_h @ Wn1[128:256] + bn1
// weight slab images (fp16), transposed [128 N x 64 K] row-major:
// We1:0-5, We2:6-7, Wn1:8-11, Wn2:12-13
__device__ __align__(16) unsigned char g_Wh[14 * 16384];

static __device__ __forceinline__ uint32_t smem_u32(const void* p) {
    uint32_t a;
    asm("{ .reg .u64 t; cvta.to.shared.u64 t, %1; cvt.u32.u64 %0, t; }" : "=r"(a) : "l"(p));
    return a;
}
static __device__ __forceinline__ void f16split(float a, float b, uint32_t& hi, uint32_t& lo) {
    __half2 h = __floats2half2_rn(a, b);
    float2 hf = __half22float2(h);
    __half2 l = __floats2half2_rn(a - hf.x, b - hf.y);
    hi = *reinterpret_cast<uint32_t*>(&h);
    lo = *reinterpret_cast<uint32_t*>(&l);
}
static __device__ __forceinline__ uint32_t f16pack(float a, float b) {
    __half2 h = __floats2half2_rn(a, b);
    return *reinterpret_cast<uint32_t*>(&h);
}

#define CPA(dst, src) asm volatile("cp.async.ca.shared.global [%0], [%1], 16;" :: "r"(dst), "l"(src))
#define CPC()         asm volatile("cp.async.commit_group;" ::: "memory")
#define CPW(n)        asm volatile("cp.async.wait_group %0;" :: "n"(n) : "memory")

static __device__ __forceinline__ void ldsm4(uint32_t addr, uint32_t* r) {
    asm volatile("ldmatrix.sync.aligned.m8n8.x4.shared.b16 {%0,%1,%2,%3}, [%4];"
                 : "=r"(r[0]), "=r"(r[1]), "=r"(r[2]), "=r"(r[3]) : "r"(addr));
}
static __device__ __forceinline__ void mma16816(float* d, const uint32_t* a, const uint32_t* b) {
    asm volatile("mma.sync.aligned.m16n8k16.row.col.f32.f16.f16.f32 "
                 "{%0,%1,%2,%3},{%4,%5,%6,%7},{%8,%9},{%0,%1,%2,%3};"
                 : "+f"(d[0]), "+f"(d[1]), "+f"(d[2]), "+f"(d[3])
                 : "r"(a[0]), "r"(a[1]), "r"(a[2]), "r"(a[3]), "r"(b[0]), "r"(b[1]));
}

// ---- shared geometry ----
#define OFF_DST  0
#define OFF_ROWS 256
#define ABUF     9216                     // 64 * 144
#define ASTR 144
#define YSTR 272
#define YF   132
// node/precompute layout (2-term A): 56320 B -> 4 CTAs/SM
#define N_AH(b)  (1024 + (b) * ABUF)
#define N_AL(b)  (1024 + 2 * ABUF + (b) * ABUF)
#define N_B      (1024 + 4 * ABUF)
#define N_SM     (1024 + 4 * ABUF + 18432)     // 56320
// edge layout (single-term A): 37888 B -> 5 CTAs/SM
#define E_A(b)   (1024 + (b) * ABUF)
#define E_B      (1024 + 2 * ABUF)
#define E_SM     (1024 + 2 * ABUF + 18432)     // 37888

#define ZACC(a) do {                                                   \
    _Pragma("unroll") for (int _m = 0; _m < 2; _m++)                   \
    _Pragma("unroll") for (int _n = 0; _n < 8; _n++)                   \
    _Pragma("unroll") for (int _q = 0; _q < 4; _q++) (a)[_m][_n][_q] = 0.f; } while (0)

// 2-term chunk (node/precompute): 8 LDSM + 32 MMA
static __device__ __forceinline__ void mma_chunk2(
        uint32_t ahb, uint32_t alb, int astride, uint32_t bb,
        int mrow, int nbase, int kb, int bkb, int lane, float acc[2][8][4]) {
    uint32_t ah[2][4], al[2][4];
    const int arow = mrow + (lane & 15);
    const int ak   = kb + (lane >> 4) * 16;
#pragma unroll
    for (int mt = 0; mt < 2; mt++) {
        uint32_t off = (uint32_t)((arow + 16 * mt) * astride + ak);
        ldsm4(ahb + off, ah[mt]);
        ldsm4(alb + off, al[mt]);
    }
    const int bn = (lane & 7) + 8 * (lane >> 4);
    const int bk = bkb + ((lane >> 3) & 1) * 16;
#pragma unroll
    for (int nt2 = 0; nt2 < 4; nt2++) {
        uint32_t bh[4];
        ldsm4(bb + (uint32_t)((nbase + 16 * nt2 + bn) * ASTR + bk), bh);
#pragma unroll
        for (int half = 0; half < 2; half++) {
            int nt = 2 * nt2 + half;
            const uint32_t* bhp = &bh[2 * half];
#pragma unroll
            for (int mt = 0; mt < 2; mt++) {
                mma16816(acc[mt][nt], ah[mt], bhp);
                mma16816(acc[mt][nt], al[mt], bhp);
            }
        }
    }
}
// single-term chunk (edge): 6 LDSM + 16 MMA
static __device__ __forceinline__ void mma_chunk1(
        uint32_t ab, int astride, uint32_t bb,
        int mrow, int nbase, int kb, int bkb, int lane, float acc[2][8][4]) {
    uint32_t ah[2][4];
    const int arow = mrow + (lane & 15);
    const int ak   = kb + (lane >> 4) * 16;
#pragma unroll
    for (int mt = 0; mt < 2; mt++)
        ldsm4(ab + (uint32_t)((arow + 16 * mt) * astride + ak), ah[mt]);
    const int bn = (lane & 7) + 8 * (lane >> 4);
    const int bk = bkb + ((lane >> 3) & 1) * 16;
#pragma unroll
    for (int nt2 = 0; nt2 < 4; nt2++) {
        uint32_t bh[4];
        ldsm4(bb + (uint32_t)((nbase + 16 * nt2 + bn) * ASTR + bk), bh);
#pragma unroll
        for (int half = 0; half < 2; half++) {
            int nt = 2 * nt2 + half;
            const uint32_t* bhp = &bh[2 * half];
#pragma unroll
            for (int mt = 0; mt < 2; mt++)
                mma16816(acc[mt][nt], ah[mt], bhp);
        }
    }
}

// ---- loaders (128 threads) ----
static __device__ __forceinline__ void load_W(uint32_t sb, int boff, int slab, int tid) {
    for (int u = tid; u < 1024; u += 128) {
        int r = u >> 3, c = u & 7;
        CPA(sb + boff + r * ASTR + c * 16, g_Wh + slab * 16384 + r * 128 + c * 16);
    }
}
static __device__ __forceinline__ void load_f32split(unsigned char* sm, int oh, int ol,
        const float* base, const int* rows, int rbase, int koff, int tid) {
    for (int u = tid; u < 1024; u += 128) {
        int r = u >> 4, c4 = u & 15;
        size_t row = rows ? (size_t)rows[r] : (size_t)(rbase + r);
        float4 v = *(const float4*)(base + row * 128 + koff + c4 * 4);
        uint2 hi, lo;
        f16split(v.x, v.y, hi.x, lo.x);
        f16split(v.z, v.w, hi.y, lo.y);
        *(uint2*)(sm + oh + r * ASTR + c4 * 8) = hi;
        *(uint2*)(sm + ol + r * ASTR + c4 * 8) = lo;
    }
}
static __device__ __forceinline__ void load_f32hi(unsigned char* sm, int oh,
        const float* base, int rbase, int koff, int tid) {
    for (int u = tid; u < 1024; u += 128) {
        int r = u >> 4, c4 = u & 15;
        float4 v = *(const float4*)(base + (size_t)(rbase + r) * 128 + koff + c4 * 4);
        uint2 hi;
        hi.x = f16pack(v.x, v.y);
        hi.y = f16pack(v.z, v.w);
        *(uint2*)(sm + oh + r * ASTR + c4 * 8) = hi;
    }
}

// ---- prep kernels ----
__global__ void zero_agg_kernel() {
    size_t stride = (size_t)gridDim.x * blockDim.x * 4;
    for (size_t i = (size_t)(blockIdx.x * blockDim.x + threadIdx.x) * 4;
         i < (size_t)NN * 128; i += stride)
        *(float4*)&g_agg[i] = make_float4(0.f, 0.f, 0.f, 0.f);
}
__global__ void prep_weights_kernel(const float* __restrict__ We1, const float* __restrict__ We2,
                                    const float* __restrict__ Wn1, const float* __restrict__ Wn2) {
    int s = blockIdx.x;
    const float* W; int slab;
    if (s < 6)       { W = We1; slab = s; }
    else if (s < 8)  { W = We2; slab = s - 6; }
    else if (s < 12) { W = Wn1; slab = s - 8; }
    else             { W = Wn2; slab = s - 12; }
    unsigned char* ph = g_Wh + s * 16384;
    int k0 = slab * 64;
    for (int p = threadIdx.x; p < 4096; p += blockDim.x) {
        int n = p >> 5, kk = (p & 31) << 1;
        float x0 = W[(size_t)(k0 + kk) * 128 + n];
        float x1 = W[(size_t)(k0 + kk + 1) * 128 + n];
        *(uint32_t*)(ph + n * 128 + kk * 2) = f16pack(x0, x1);
    }
}

// ---- precompute: U, V (+be1), P (+bn1) ----
__global__ __launch_bounds__(128, 4)
void precompute_kernel(const float* __restrict__ node_h,
                       const float* __restrict__ be1, const float* __restrict__ bn1) {
    extern __shared__ __align__(1024) unsigned char sm[];
    const uint32_t sb = smem_u32(sm);
    const int tid = threadIdx.x, wid = tid >> 5, lane = tid & 31;
    const int nbase0 = blockIdx.x << 6;
    const int mrow = (wid >> 1) << 5;
    const int nbase = (wid & 1) << 6;

    int* rowsS = (int*)(sm + OFF_ROWS);
    if (tid < 64) { int n = nbase0 + tid; if (n >= NN) n = NN - 1; rowsS[tid] = n; }
    __syncthreads();

    load_f32split(sm, N_AH(0), N_AL(0), node_h, rowsS, 0, 0, tid);
    load_f32split(sm, N_AH(1), N_AL(1), node_h, rowsS, 0, 64, tid);
    __syncthreads();

    const int ra = mrow + (lane >> 2);
    const int cc = nbase + 2 * (lane & 3);
    const int w0[3] = {0, 2, 10}, w1[3] = {1, 3, 11};
    float* outs[3] = {g_U, g_V, g_P};
#pragma unroll 1
    for (int t = 0; t < 3; t++) {
        float acc[2][8][4]; ZACC(acc);
        load_W(sb, N_B, w0[t], tid); CPC(); CPW(0);
        __syncthreads();
        for (int c = 0; c < 4; c++)
            mma_chunk2(sb + N_AH(0), sb + N_AL(0), ASTR, sb + N_B,
                       mrow, nbase, c * 32, c * 32, lane, acc);
        __syncthreads();
        load_W(sb, N_B, w1[t], tid); CPC(); CPW(0);
        __syncthreads();
        for (int c = 0; c < 4; c++)
            mma_chunk2(sb + N_AH(1), sb + N_AL(1), ASTR, sb + N_B,
                       mrow, nbase, c * 32, c * 32, lane, acc);
        __syncthreads();
        float* op = outs[t];
        const float* badd = (t == 1) ? be1 : ((t == 2) ? bn1 : nullptr);
#pragma unroll
        for (int mt = 0; mt < 2; mt++)
#pragma unroll
            for (int h = 0; h < 2; h++) {
                int r = ra + 16 * mt + 8 * h;
                int n = nbase0 + r;
                if (n < NN) {
#pragma unroll
                    for (int nt = 0; nt < 8; nt++) {
                        int c = cc + 8 * nt;
                        float b0 = badd ? __ldg(&badd[c])     : 0.f;
                        float b1 = badd ? __ldg(&badd[c + 1]) : 0.f;
                        *(float2*)(op + (size_t)n * 128 + c) =
                            make_float2(acc[mt][nt][2 * h] + b0,
                                        acc[mt][nt][2 * h + 1] + b1);
                    }
                }
            }
    }
}

// ---- edge kernel: single-fp16 A, GEMM1 = e@Wc, U/V(+be1) in epilogue, v4-red ----
__global__ __launch_bounds__(128, 5)
void edge_kernel(const float* __restrict__ edge_h,
                 const int* __restrict__ src, const int* __restrict__ dst,
                 const float* __restrict__ be2) {
    extern __shared__ __align__(1024) unsigned char sm[];
    const uint32_t sb = smem_u32(sm);
    const int tid = threadIdx.x, wid = tid >> 5, lane = tid & 31;
    const int ebase = blockIdx.x << 6;
    const int mrow = (wid >> 1) << 5;
    const int nbase = (wid & 1) << 6;

    int* srcS = (int*)(sm + OFF_ROWS);
    int* dstS = (int*)(sm + OFF_DST);
    if (tid < 64) { srcS[tid] = src[ebase + tid]; dstS[tid] = dst[ebase + tid]; }

    load_W(sb, E_B, 4, tid); CPC();
    load_f32hi(sm, E_A(0), edge_h, ebase, 0, tid);
    load_f32hi(sm, E_A(1), edge_h, ebase, 64, tid);

    float acc[2][8][4]; ZACC(acc);
    CPW(0);
    __syncthreads();
    for (int c = 0; c < 4; c++)
        mma_chunk1(sb + E_A(0), ASTR, sb + E_B, mrow, nbase, c * 32, c * 32, lane, acc);
    __syncthreads();
    load_W(sb, E_B, 5, tid); CPC(); CPW(0);
    __syncthreads();
    for (int c = 0; c < 4; c++)
        mma_chunk1(sb + E_A(1), ASTR, sb + E_B, mrow, nbase, c * 32, c * 32, lane, acc);
    __syncthreads();                       // A + B free
    load_W(sb, E_B, 6, tid); CPC();        // We2 k0 streams in during epilogue

    // epilogue1: acc + U[src] + V[dst] (be1 folded in V) -> relu -> fp16 -> Y
    const int ra = mrow + (lane >> 2);
    const int cc = nbase + 2 * (lane & 3);
#pragma unroll
    for (int mt = 0; mt < 2; mt++)
#pragma unroll
        for (int h = 0; h < 2; h++) {
            int r = ra + 16 * mt + 8 * h;
            const float* up = g_U + (size_t)srcS[r] * 128;
            const float* vp = g_V + (size_t)dstS[r] * 128;
#pragma unroll
            for (int nt = 0; nt < 8; nt++) {
                int c = cc + 8 * nt;
                float2 u = __ldg((const float2*)(up + c));
                float2 v = __ldg((const float2*)(vp + c));
                float v0 = fmaxf(acc[mt][nt][2 * h]     + u.x + v.x, 0.f);
                float v1 = fmaxf(acc[mt][nt][2 * h + 1] + u.y + v.y, 0.f);
                *(uint32_t*)(sm + E_A(0) + r * YSTR + c * 2) = f16pack(v0, v1);
            }
        }
    ZACC(acc);
    CPW(0);
    __syncthreads();
    // GEMM2 part 1: Y @ We2 k0
    for (int c = 0; c < 4; c++)
        mma_chunk1(sb + E_A(0), YSTR, sb + E_B, mrow, nbase, c * 32, c * 32, lane, acc);
    __syncthreads();
    load_W(sb, E_B, 7, tid); CPC(); CPW(0);
    __syncthreads();
    // GEMM2 part 2: Y @ We2 k64
    for (int c = 0; c < 4; c++)
        mma_chunk1(sb + E_A(0), YSTR, sb + E_B, mrow, nbase, (4 + c) * 32, c * 32, lane, acc);
    __syncthreads();   // done reading Y/B before staging overwrites

    // epilogue2: stage y2 fp32 -> smem (overlaps A+B), coalesced red.v4 (+be2)
    float* stage = (float*)(sm + 1024);
#pragma unroll
    for (int mt = 0; mt < 2; mt++)
#pragma unroll
        for (int h = 0; h < 2; h++) {
            int r = ra + 16 * mt + 8 * h;
            float* row = stage + r * YF;
#pragma unroll
            for (int nt = 0; nt < 8; nt++) {
                int c = cc + 8 * nt;
                row[c]     = acc[mt][nt][2 * h];
                row[c + 1] = acc[mt][nt][2 * h + 1];
            }
        }
    __syncthreads();
    const float4 b2 = __ldg((const float4*)(be2 + lane * 4));
#pragma unroll 1
    for (int i = 0; i < 16; i++) {
        int r = wid * 16 + i;
        float4 v = *(const float4*)(stage + r * YF + lane * 4);
        v.x += b2.x; v.y += b2.y; v.z += b2.z; v.w += b2.w;
        float* gp = g_agg + (size_t)dstS[r] * 128 + lane * 4;
        asm volatile("red.global.add.v4.f32 [%0], {%1,%2,%3,%4};"
                     :: "l"(gp), "f"(v.x), "f"(v.y), "f"(v.z), "f"(v.w) : "memory");
    }
}

// ---- node kernel: GEMM1 = agg@Wn1[0:128] (2-term), P(+bn1) in epilogue ----
__global__ __launch_bounds__(128, 4)
void node_kernel(const float* __restrict__ bn2, float* __restrict__ out) {
    extern __shared__ __align__(1024) unsigned char sm[];
    const uint32_t sb = smem_u32(sm);
    const int tid = threadIdx.x, wid = tid >> 5, lane = tid & 31;
    const int nbase0 = blockIdx.x << 6;
    const int mrow = (wid >> 1) << 5;
    const int nbase = (wid & 1) << 6;

    int* rowsS = (int*)(sm + OFF_ROWS);
    if (tid < 64) { int n = nbase0 + tid; if (n >= NN) n = NN - 1; rowsS[tid] = n; }
    __syncthreads();

    load_W(sb, N_B, 8, tid); CPC();
    load_f32split(sm, N_AH(0), N_AL(0), g_agg, rowsS, 0, 0, tid);
    load_f32split(sm, N_AH(1), N_AL(1), g_agg, rowsS, 0, 64, tid);

    float acc[2][8][4]; ZACC(acc);
    CPW(0);
    __syncthreads();
    for (int c = 0; c < 4; c++)
        mma_chunk2(sb + N_AH(0), sb + N_AL(0), ASTR, sb + N_B,
                   mrow, nbase, c * 32, c * 32, lane, acc);
    __syncthreads();
    load_W(sb, N_B, 9, tid); CPC(); CPW(0);
    __syncthreads();
    for (int c = 0; c < 4; c++)
        mma_chunk2(sb + N_AH(1), sb + N_AL(1), ASTR, sb + N_B,
                   mrow, nbase, c * 32, c * 32, lane, acc);
    __syncthreads();
    load_W(sb, N_B, 12, tid); CPC();

    const int ra = mrow + (lane >> 2);
    const int cc = nbase + 2 * (lane & 3);
#pragma unroll
    for (int mt = 0; mt < 2; mt++)
#pragma unroll
        for (int h = 0; h < 2; h++) {
            int r = ra + 16 * mt + 8 * h;
            int n = nbase0 + r; if (n >= NN) n = NN - 1;
            const float* pp = g_P + (size_t)n * 128;
#pragma unroll
            for (int nt = 0; nt < 8; nt++) {
                int c = cc + 8 * nt;
                float2 p = __ldg((const float2*)(pp + c));
                float v0 = fmaxf(acc[mt][nt][2 * h]     + p.x, 0.f);
                float v1 = fmaxf(acc[mt][nt][2 * h + 1] + p.y, 0.f);
                uint32_t hv, lv;
                f16split(v0, v1, hv, lv);
                *(uint32_t*)(sm + N_AH(0) + r * YSTR + c * 2) = hv;
                *(uint32_t*)(sm + N_AL(0) + r * YSTR + c * 2) = lv;
            }
        }
    ZACC(acc);
    CPW(0);
    __syncthreads();
    for (int c = 0; c < 4; c++)
        mma_chunk2(sb + N_AH(0), sb + N_AL(0), YSTR, sb + N_B,
                   mrow, nbase, c * 32, c * 32, lane, acc);
    __syncthreads();
    load_W(sb, N_B, 13, tid); CPC(); CPW(0);
    __syncthreads();
    for (int c = 0; c < 4; c++)
        mma_chunk2(sb + N_AH(0), sb + N_AL(0), YSTR, sb + N_B,
                   mrow, nbase, (4 + c) * 32, c * 32, lane, acc);

#pragma unroll
    for (int mt = 0; mt < 2; mt++)
#pragma unroll
        for (int h = 0; h < 2; h++) {
            int r = ra + 16 * mt + 8 * h;
            int n = nbase0 + r;
            if (n < NN) {
#pragma unroll
                for (int nt = 0; nt < 8; nt++) {
                    int c = cc + 8 * nt;
                    *(float2*)(out + (size_t)n * 128 + c) =
                        make_float2(acc[mt][nt][2 * h]     + __ldg(&bn2[c]),
                                    acc[mt][nt][2 * h + 1] + __ldg(&bn2[c + 1]));
                }
            }
        }
}

extern "C" void kernel_launch(void* const* d_in, const int* in_sizes, int n_in,
                              void* d_out, int out_size) {
    const float* node_h = (const float*)d_in[0];
    const float* edge_h = (const float*)d_in[1];
    const int*   src    = (const int*)d_in[2];
    const int*   dst    = (const int*)d_in[3];
    const float* We1    = (const float*)d_in[4];
    const float* be1    = (const float*)d_in[5];
    const float* We2    = (const float*)d_in[6];
    const float* be2    = (const float*)d_in[7];
    const float* Wn1    = (const float*)d_in[8];
    const float* bn1    = (const float*)d_in[9];
    const float* Wn2    = (const float*)d_in[10];
    const float* bn2    = (const float*)d_in[11];
    float* out = (float*)d_out;

    cudaFuncSetAttribute(precompute_kernel, cudaFuncAttributeMaxDynamicSharedMemorySize, N_SM);
    cudaFuncSetAttribute(edge_kernel, cudaFuncAttributeMaxDynamicSharedMemorySize, E_SM);
    cudaFuncSetAttribute(node_kernel, cudaFuncAttributeMaxDynamicSharedMemorySize, N_SM);

    zero_agg_kernel<<<1024, 256>>>();
    prep_weights_kernel<<<14, 256>>>(We1, We2, Wn1, Wn2);
    precompute_kernel<<<(NN + 63) / 64, 128, N_SM>>>(node_h, be1, bn1);
    edge_kernel<<<NE / 64, 128, E_SM>>>(edge_h, src, dst, be2);
    node_kernel<<<(NN + 63) / 64, 128, N_SM>>>(bn2, out);
}